// round 5
// baseline (speedup 1.0000x reference)
#include <cuda_runtime.h>
#include <cuda_fp16.h>
#include <math.h>
#include <stdint.h>

#define SL   2048
#define DM   512
#define DI   1024
#define DS   16
#define DXZ  2048   // 2*DI
#define NSP  1056   // DI + 2*DS
#define NSP_PAD 1152
#define NCH  16
#define CL   128    // SL / NCH
#define WSCALE 64.0f
#define INV_WSCALE 0.015625f

// ---------------- fp32 scratch ----------------
__device__ float g_xz[2 * SL * DXZ];      // in-proj output: x_ssm | z
__device__ float g_xconv[2 * SL * DI];    // post depthwise conv (pre-silu)
__device__ float g_sp[2 * SL * NSP];      // xp-proj output: delta | B | C
__device__ float g_dt[2 * SL * DI];       // softplus(delta @ dtW + dtb)
// scan chunk scratch
__device__ float g_dtsum[2 * DI * NCH];
__device__ float g_hpart[2 * DI * NCH * DS];
__device__ float g_hinit[2 * DI * NCH * DS];

// ---------------- fp16 activations (A operands, single precision copy) ----------------
__device__ __align__(16) __half g_X2h[2 * SL * DM];
__device__ __align__(16) __half g_sxh[2 * SL * DI];
__device__ __align__(16) __half g_dh [2 * SL * DI];
__device__ __align__(16) __half g_yzh[2 * SL * DI];
__device__ __align__(16) __half g_cth[SL * 2 * DM];
// ---------------- fp16 hi/lo transposed scaled weights [Npad][K] ----------------
__device__ __align__(16) __half g_inWh[2 * DXZ * DM],     g_inWl[2 * DXZ * DM];
__device__ __align__(16) __half g_xpWh[2 * NSP_PAD * DI], g_xpWl[2 * NSP_PAD * DI];
__device__ __align__(16) __half g_dtWh[2 * DI * DI],      g_dtWl[2 * DI * DI];
__device__ __align__(16) __half g_outWh[2 * DM * DI],     g_outWl[2 * DM * DI];
__device__ __align__(16) __half g_fuWh[DM * 2 * DM],      g_fuWl[DM * 2 * DM];

// ---------------- helpers ----------------
__device__ __forceinline__ float siluf(float v) { return v / (1.0f + __expf(-v)); }

__device__ __forceinline__ uint32_t smem_u32(const void* p) {
    uint32_t a;
    asm("{ .reg .u64 t; cvta.to.shared.u64 t, %1; cvt.u32.u64 %0, t; }" : "=r"(a) : "l"(p));
    return a;
}
__device__ __forceinline__ void cp16(uint32_t dst, const void* src) {
    asm volatile("cp.async.cg.shared.global [%0], [%1], 16;" :: "r"(dst), "l"(src));
}
__device__ __forceinline__ void cp_commit() {
    asm volatile("cp.async.commit_group;" ::: "memory");
}
__device__ __forceinline__ void cp_wait2() {
    asm volatile("cp.async.wait_group 2;" ::: "memory");
}

#define LDSM_X4(r0, r1, r2, r3, addr) \
    asm volatile("ldmatrix.sync.aligned.m8n8.x4.shared.b16 {%0,%1,%2,%3}, [%4];" \
                 : "=r"(r0), "=r"(r1), "=r"(r2), "=r"(r3) : "r"(addr))

#define MMA16816(d, a, b) \
    asm volatile("mma.sync.aligned.m16n8k16.row.col.f32.f16.f16.f32 " \
                 "{%0,%1,%2,%3}, {%4,%5,%6,%7}, {%8,%9}, {%0,%1,%2,%3};" \
                 : "+f"((d)[0]), "+f"((d)[1]), "+f"((d)[2]), "+f"((d)[3]) \
                 : "r"((a)[0]), "r"((a)[1]), "r"((a)[2]), "r"((a)[3]), \
                   "r"((b)[0]), "r"((b)[1]))

#define SWZ(o) ((o) ^ (((o) >> 3) & 0x70))

// ---------------- prepare: x -> fwd + reversed bwd fp16 ----------------
__global__ void k_prepare(const float* __restrict__ x) {
    int idx = blockIdx.x * blockDim.x + threadIdx.x;
    if (idx < SL * DM) {
        int l = idx / DM, d = idx % DM;
        __half h = __float2half(x[idx]);
        g_X2h[idx] = h;
        g_X2h[(size_t)SL * DM + (size_t)(SL - 1 - l) * DM + d] = h;
    }
}

// ---------------- causal depthwise conv (K=4); fp32 xconv + fp16 silu ----------------
__global__ void k_conv(const float* __restrict__ fcw, const float* __restrict__ fcb,
                       const float* __restrict__ bcw, const float* __restrict__ bcb) {
    int idx = blockIdx.x * blockDim.x + threadIdx.x;
    if (idx >= 2 * SL * DI) return;
    int b = idx / (SL * DI);
    int r = idx - b * SL * DI;
    int l = r / DI, d = r % DI;
    const float* cw = b ? bcw : fcw;
    const float* cb = b ? bcb : fcb;
    const float* xs = g_xz + (size_t)b * SL * DXZ;
    float acc = cb[d];
#pragma unroll
    for (int k = 0; k < 4; k++) {
        int ls = l + k - 3;
        if (ls >= 0) acc += cw[d * 4 + k] * xs[(size_t)ls * DXZ + d];
    }
    g_xconv[idx] = acc;
    g_sxh[idx] = __float2half(siluf(acc));
}

// ---------------- fused weight transpose + scale + hi/lo split (all 9 weights) ----------------
struct WtJobs {
    const float* W[9];
    __half* Bh[9];
    __half* Bl[9];
    int K[9], N[9], bx[9];
    int ofs[10];
};

__global__ void k_wt_all(WtJobs jw) {
    __shared__ float s[32][33];
    int bxg = blockIdx.x;
    int j = 0;
#pragma unroll
    for (int q = 0; q < 9; q++) if (bxg >= jw.ofs[q + 1]) j = q + 1;
    int local = bxg - jw.ofs[j];
    int K = jw.K[j], N = jw.N[j], bxn = jw.bx[j];
    int nb = (local % bxn) * 32, kb = (local / bxn) * 32;
    const float* __restrict__ W = jw.W[j];
    __half* __restrict__ hiT = jw.Bh[j];
    __half* __restrict__ loT = jw.Bl[j];
    int tx = threadIdx.x, ty = threadIdx.y;
#pragma unroll
    for (int q = 0; q < 32; q += 8) {
        int k = kb + ty + q, n = nb + tx;
        s[ty + q][tx] = (n < N) ? W[(size_t)k * N + n] * WSCALE : 0.0f;
    }
    __syncthreads();
#pragma unroll
    for (int q = 0; q < 32; q += 8) {
        int n = nb + ty + q, k = kb + tx;
        float v = s[tx][ty + q];
        __half h = __float2half(v);
        __half l = __float2half(v - __half2float(h));
        hiT[(size_t)n * K + k] = h;
        loT[(size_t)n * K + k] = l;
    }
}

// ---------------- fp16 2-term GEMM: C = A @ (W*64)^T / 64 + bias ----------------
// CTA tile 128x128, K-slab 64, 8 warps (4m x 2n) each 32x64, 3-stage cp.async pipeline.
struct TArgs {
    const __half *Ah[2], *Bh[2], *Bl[2];
    const float* bias[2];
    float* C[2];
    __half* Dh[2];
    int M, N, K, ldc, ldd, dlim;
    int rev[2];
};

#define TILE_B  16384      // 128 x 64 fp16
#define STAGE_B (3 * TILE_B)
#define GEMM_SMEM (3 * STAGE_B)   // 147456

__device__ __forceinline__ void load_slab(uint32_t sdst,
    const __half* Ah, const __half* Bh, const __half* Bl,
    int m0, int n0, int K, int kslab, int tid)
{
    const __half* srcs[3] = { Ah + (size_t)m0 * K, Bh + (size_t)n0 * K, Bl + (size_t)n0 * K };
    const int kof = kslab * 64;
#pragma unroll
    for (int t = 0; t < 3; t++) {
#pragma unroll
        for (int i = 0; i < 4; i++) {
            int idx = tid + i * 256;
            int r = idx >> 3, c = idx & 7;
            uint32_t dst = sdst + t * TILE_B + SWZ(r * 128 + c * 16);
            cp16(dst, srcs[t] + (size_t)r * K + kof + c * 8);
        }
    }
}

// EPI: 0 none, 1 softplus.  MODE: 0 fp32 C only, 1 fp32 C + fp16 D (cols<dlim), 2 fp16 D only.
template <int EPI, int MODE>
__global__ void __launch_bounds__(256, 1) k_mma_gemm(TArgs ga) {
    extern __shared__ __align__(1024) char smem[];
    const int bz = blockIdx.z;
    const __half* __restrict__ Ah = ga.Ah[bz];
    const __half* __restrict__ Bh = ga.Bh[bz];
    const __half* __restrict__ Bl = ga.Bl[bz];
    const float* __restrict__ bias = ga.bias[bz];
    float* __restrict__ C = ga.C[bz];
    __half* __restrict__ D = ga.Dh[bz];
    const int K = ga.K, N = ga.N, ldc = ga.ldc, ldd = ga.ldd, rev = ga.rev[bz];
    const int m0 = blockIdx.y * 128, n0 = blockIdx.x * 128;

    const int tid = threadIdx.x, wid = tid >> 5, lane = tid & 31;
    const int wm = (wid & 3) * 32;
    const int wn = (wid >> 2) * 64;
    const uint32_t sb = smem_u32(smem);

    float acc[2][8][4];
#pragma unroll
    for (int i = 0; i < 2; i++)
#pragma unroll
        for (int j = 0; j < 8; j++)
#pragma unroll
            for (int q = 0; q < 4; q++) acc[i][j][q] = 0.0f;

    const int nslab = K / 64;

    load_slab(sb, Ah, Bh, Bl, m0, n0, K, 0, tid);
    cp_commit();
    if (nslab > 1) load_slab(sb + STAGE_B, Ah, Bh, Bl, m0, n0, K, 1, tid);
    cp_commit();
    if (nslab > 2) load_slab(sb + 2 * STAGE_B, Ah, Bh, Bl, m0, n0, K, 2, tid);
    cp_commit();

    const int a_row = (lane & 15);
    const int a_kc  = (lane >> 4) * 16;
    const int b_row = (lane & 7) + ((lane >> 4) << 3);
    const int b_kc  = ((lane >> 3) & 1) * 16;

    int stage = 0;
    for (int sl = 0; sl < nslab; sl++) {
        cp_wait2();
        __syncthreads();
        const uint32_t st = sb + stage * STAGE_B;
        const uint32_t stA = st, stBh = st + TILE_B, stBl = st + 2 * TILE_B;

#pragma unroll
        for (int ks = 0; ks < 4; ks++) {
            uint32_t ah[2][4];
#pragma unroll
            for (int mi = 0; mi < 2; mi++) {
                uint32_t off = SWZ((wm + mi * 16 + a_row) * 128 + ks * 32 + a_kc);
                LDSM_X4(ah[mi][0], ah[mi][1], ah[mi][2], ah[mi][3], stA + off);
            }
            uint32_t bh[8][2], bl[8][2];
#pragma unroll
            for (int jj = 0; jj < 4; jj++) {
                uint32_t off = SWZ((wn + jj * 16 + b_row) * 128 + ks * 32 + b_kc);
                uint32_t r0, r1, r2, r3;
                LDSM_X4(r0, r1, r2, r3, stBh + off);
                bh[jj * 2][0] = r0; bh[jj * 2][1] = r1;
                bh[jj * 2 + 1][0] = r2; bh[jj * 2 + 1][1] = r3;
                LDSM_X4(r0, r1, r2, r3, stBl + off);
                bl[jj * 2][0] = r0; bl[jj * 2][1] = r1;
                bl[jj * 2 + 1][0] = r2; bl[jj * 2 + 1][1] = r3;
            }
#pragma unroll
            for (int mi = 0; mi < 2; mi++)
#pragma unroll
                for (int nj = 0; nj < 8; nj++) {
                    MMA16816(acc[mi][nj], ah[mi], bh[nj]);
                    MMA16816(acc[mi][nj], ah[mi], bl[nj]);
                }
        }
        __syncthreads();
        if (sl + 3 < nslab)
            load_slab(sb + stage * STAGE_B, Ah, Bh, Bl, m0, n0, K, sl + 3, tid);
        cp_commit();
        stage = (stage == 2) ? 0 : stage + 1;
    }

    // epilogue
    const int gid = lane >> 2, tig = lane & 3;
#pragma unroll
    for (int mi = 0; mi < 2; mi++) {
        int mb = m0 + wm + mi * 16 + gid;
        int r1 = rev ? (ga.M - 1 - mb) : mb;
        int r2 = rev ? (ga.M - 1 - (mb + 8)) : (mb + 8);
#pragma unroll
        for (int nj = 0; nj < 8; nj++) {
            int nc = n0 + wn + nj * 8 + tig * 2;
            if (nc < N) {
                float b0 = bias[nc], b1 = bias[nc + 1];
                float v0 = acc[mi][nj][0] * INV_WSCALE + b0;
                float v1 = acc[mi][nj][1] * INV_WSCALE + b1;
                float v2 = acc[mi][nj][2] * INV_WSCALE + b0;
                float v3 = acc[mi][nj][3] * INV_WSCALE + b1;
                if (EPI == 1) {
                    v0 = (v0 > 20.0f) ? v0 : log1pf(__expf(v0));
                    v1 = (v1 > 20.0f) ? v1 : log1pf(__expf(v1));
                    v2 = (v2 > 20.0f) ? v2 : log1pf(__expf(v2));
                    v3 = (v3 > 20.0f) ? v3 : log1pf(__expf(v3));
                }
                if (MODE == 0 || MODE == 1) {
                    *(float2*)&C[(size_t)r1 * ldc + nc] = make_float2(v0, v1);
                    *(float2*)&C[(size_t)r2 * ldc + nc] = make_float2(v2, v3);
                }
                if ((MODE == 1 && nc < ga.dlim) || MODE == 2) {
                    *(__half2*)&D[(size_t)r1 * ldd + nc] = __floats2half2_rn(v0, v1);
                    *(__half2*)&D[(size_t)r2 * ldd + nc] = __floats2half2_rn(v2, v3);
                }
            }
        }
    }
}

// ---------------- chunked selective scan ----------------
__global__ void k_scanA(const float* __restrict__ A_log) {
    __shared__ float sB[CL][DS];
    const int b = blockIdx.z, ch = blockIdx.y;
    const int d = blockIdx.x * 128 + threadIdx.x;
    const float* __restrict__ spp = g_sp + (size_t)b * SL * NSP;
    for (int i = threadIdx.x; i < CL * DS; i += 128) {
        int l = i >> 4, s = i & 15;
        sB[l][s] = spp[(size_t)(ch * CL + l) * NSP + DI + s];
    }
    __syncthreads();
    float Ac[DS];
#pragma unroll
    for (int s = 0; s < DS; s++) Ac[s] = -__expf(A_log[d * DS + s]);
    float h[DS];
#pragma unroll
    for (int s = 0; s < DS; s++) h[s] = 0.0f;
    float dts = 0.0f;
    const float* __restrict__ dtp = g_dt + (size_t)b * SL * DI;
    const float* __restrict__ xcp = g_xconv + (size_t)b * SL * DI;
    for (int l = 0; l < CL; l++) {
        int gl = ch * CL + l;
        float dt = dtp[(size_t)gl * DI + d];
        float xv = xcp[(size_t)gl * DI + d];
        dts += dt;
        float du = dt * xv;
#pragma unroll
        for (int s = 0; s < DS; s++) h[s] = __expf(dt * Ac[s]) * h[s] + du * sB[l][s];
    }
    size_t base = ((size_t)(b * DI + d) * NCH + ch) * DS;
#pragma unroll
    for (int s = 0; s < DS; s++) g_hpart[base + s] = h[s];
    g_dtsum[(size_t)(b * DI + d) * NCH + ch] = dts;
}

__global__ void k_scanB(const float* __restrict__ A_log) {
    int idx = blockIdx.x * 256 + threadIdx.x;
    if (idx >= 2 * DI * DS) return;
    int s = idx & 15;
    int d = (idx >> 4) & (DI - 1);
    int b = idx >> 14;
    float Ac = -__expf(A_log[d * DS + s]);
    float h = 0.0f;
    size_t bd = (size_t)(b * DI + d) * NCH;
    for (int ch = 0; ch < NCH; ch++) {
        g_hinit[(bd + ch) * DS + s] = h;
        h = __expf(g_dtsum[bd + ch] * Ac) * h + g_hpart[(bd + ch) * DS + s];
    }
}

__global__ void k_scanC(const float* __restrict__ A_log, const float* __restrict__ Dp) {
    __shared__ float sB[CL][DS];
    __shared__ float sC[CL][DS];
    const int b = blockIdx.z, ch = blockIdx.y;
    const int d = blockIdx.x * 128 + threadIdx.x;
    const float* __restrict__ spp = g_sp + (size_t)b * SL * NSP;
    for (int i = threadIdx.x; i < CL * DS; i += 128) {
        int l = i >> 4, s = i & 15;
        sB[l][s] = spp[(size_t)(ch * CL + l) * NSP + DI + s];
        sC[l][s] = spp[(size_t)(ch * CL + l) * NSP + DI + DS + s];
    }
    __syncthreads();
    float Ac[DS];
#pragma unroll
    for (int s = 0; s < DS; s++) Ac[s] = -__expf(A_log[d * DS + s]);
    float h[DS];
    size_t hbase = ((size_t)(b * DI + d) * NCH + ch) * DS;
#pragma unroll
    for (int s = 0; s < DS; s++) h[s] = g_hinit[hbase + s];
    const float Dv = Dp[d];
    const float* __restrict__ dtp = g_dt + (size_t)b * SL * DI;
    const float* __restrict__ xcp = g_xconv + (size_t)b * SL * DI;
    const float* __restrict__ zp  = g_xz + (size_t)b * SL * DXZ + DI;
    __half* __restrict__ yh = g_yzh + (size_t)b * SL * DI;
    for (int l = 0; l < CL; l++) {
        int gl = ch * CL + l;
        float dt = dtp[(size_t)gl * DI + d];
        float xv = xcp[(size_t)gl * DI + d];
        float du = dt * xv;
        float y = Dv * xv;
#pragma unroll
        for (int s = 0; s < DS; s++) {
            h[s] = __expf(dt * Ac[s]) * h[s] + du * sB[l][s];
            y += h[s] * sC[l][s];
        }
        float zv = zp[(size_t)gl * DXZ + d];
        yh[(size_t)gl * DI + d] = __float2half(y * siluf(zv));
    }
}

// ---------------- host orchestration ----------------
extern "C" void kernel_launch(void* const* d_in, const int* in_sizes, int n_in,
                              void* d_out, int out_size) {
    const float* x = (const float*)d_in[0];
    const float* inW[2]  = {(const float*)d_in[1],  (const float*)d_in[11]};
    const float* inb[2]  = {(const float*)d_in[2],  (const float*)d_in[12]};
    const float* cw[2]   = {(const float*)d_in[3],  (const float*)d_in[13]};
    const float* cb[2]   = {(const float*)d_in[4],  (const float*)d_in[14]};
    const float* xpW[2]  = {(const float*)d_in[5],  (const float*)d_in[15]};
    const float* xpb[2]  = {(const float*)d_in[6],  (const float*)d_in[16]};
    const float* dtW[2]  = {(const float*)d_in[7],  (const float*)d_in[17]};
    const float* dtb[2]  = {(const float*)d_in[8],  (const float*)d_in[18]};
    const float* outW[2] = {(const float*)d_in[9],  (const float*)d_in[19]};
    const float* outb[2] = {(const float*)d_in[10], (const float*)d_in[20]};
    const float* A_log   = (const float*)d_in[21];
    const float* Dp      = (const float*)d_in[22];
    const float* fuW     = (const float*)d_in[23];
    const float* fub     = (const float*)d_in[24];
    float* out = (float*)d_out;

    cudaFuncSetAttribute(k_mma_gemm<0,0>, cudaFuncAttributeMaxDynamicSharedMemorySize, GEMM_SMEM);
    cudaFuncSetAttribute(k_mma_gemm<0,1>, cudaFuncAttributeMaxDynamicSharedMemorySize, GEMM_SMEM);
    cudaFuncSetAttribute(k_mma_gemm<0,2>, cudaFuncAttributeMaxDynamicSharedMemorySize, GEMM_SMEM);
    cudaFuncSetAttribute(k_mma_gemm<1,0>, cudaFuncAttributeMaxDynamicSharedMemorySize, GEMM_SMEM);

    float *xz, *sp, *dtbuf;
    __half *X2h, *sxh, *dh, *yzh, *cth;
    __half *inWh, *inWl, *xpWh, *xpWl, *dtWh, *dtWl, *outWh, *outWl, *fuWh, *fuWl;
    cudaGetSymbolAddress((void**)&xz, g_xz);
    cudaGetSymbolAddress((void**)&sp, g_sp);
    cudaGetSymbolAddress((void**)&dtbuf, g_dt);
    cudaGetSymbolAddress((void**)&X2h, g_X2h);
    cudaGetSymbolAddress((void**)&sxh, g_sxh);
    cudaGetSymbolAddress((void**)&dh, g_dh);
    cudaGetSymbolAddress((void**)&yzh, g_yzh);
    cudaGetSymbolAddress((void**)&cth, g_cth);
    cudaGetSymbolAddress((void**)&inWh, g_inWh);   cudaGetSymbolAddress((void**)&inWl, g_inWl);
    cudaGetSymbolAddress((void**)&xpWh, g_xpWh);   cudaGetSymbolAddress((void**)&xpWl, g_xpWl);
    cudaGetSymbolAddress((void**)&dtWh, g_dtWh);   cudaGetSymbolAddress((void**)&dtWl, g_dtWl);
    cudaGetSymbolAddress((void**)&outWh, g_outWh); cudaGetSymbolAddress((void**)&outWl, g_outWl);
    cudaGetSymbolAddress((void**)&fuWh, g_fuWh);   cudaGetSymbolAddress((void**)&fuWl, g_fuWl);

    // 0. fused weight transpose + scale + split (9 jobs, 1 launch)
    {
        WtJobs jw;
        const float* Ws[9] = {inW[0], inW[1], xpW[0], xpW[1], dtW[0], dtW[1], outW[0], outW[1], fuW};
        __half* Hs[9] = {inWh, inWh + (size_t)DXZ * DM, xpWh, xpWh + (size_t)NSP_PAD * DI,
                         dtWh, dtWh + (size_t)DI * DI, outWh, outWh + (size_t)DM * DI, fuWh};
        __half* Ls[9] = {inWl, inWl + (size_t)DXZ * DM, xpWl, xpWl + (size_t)NSP_PAD * DI,
                         dtWl, dtWl + (size_t)DI * DI, outWl, outWl + (size_t)DM * DI, fuWl};
        int Ks[9]  = {DM, DM, DI, DI, DI, DI, DI, DI, 2 * DM};
        int Ns[9]  = {DXZ, DXZ, NSP, NSP, DI, DI, DM, DM, DM};
        int Nps[9] = {DXZ, DXZ, NSP_PAD, NSP_PAD, DI, DI, DM, DM, DM};
        int ofs = 0;
        jw.ofs[0] = 0;
        for (int j = 0; j < 9; j++) {
            jw.W[j] = Ws[j]; jw.Bh[j] = Hs[j]; jw.Bl[j] = Ls[j];
            jw.K[j] = Ks[j]; jw.N[j] = Ns[j]; jw.bx[j] = Nps[j] / 32;
            ofs += (Nps[j] / 32) * (Ks[j] / 32);
            jw.ofs[j + 1] = ofs;
        }
        k_wt_all<<<ofs, dim3(32, 8)>>>(jw);
    }

    // 1. prepare inputs
    k_prepare<<<(SL * DM + 255) / 256, 256>>>(x);

    // 2. in-projection: [2048 x 2048], K=512
    {
        TArgs ga = {};
        for (int b = 0; b < 2; b++) {
            ga.Ah[b] = X2h + (size_t)b * SL * DM;
            ga.Bh[b] = inWh + (size_t)b * DXZ * DM; ga.Bl[b] = inWl + (size_t)b * DXZ * DM;
            ga.bias[b] = inb[b];
            ga.C[b] = xz + (size_t)b * SL * DXZ;
            ga.rev[b] = 0;
        }
        ga.M = SL; ga.N = DXZ; ga.K = DM; ga.ldc = DXZ;
        k_mma_gemm<0,0><<<dim3(DXZ / 128, SL / 128, 2), 256, GEMM_SMEM>>>(ga);
    }

    // 3. depthwise conv + silu (fp16 out)
    k_conv<<<(2 * SL * DI + 255) / 256, 256>>>(cw[0], cb[0], cw[1], cb[1]);

    // 4. xp-projection: fp32 sp + fused fp16 delta split
    {
        TArgs ga = {};
        for (int b = 0; b < 2; b++) {
            ga.Ah[b] = sxh + (size_t)b * SL * DI;
            ga.Bh[b] = xpWh + (size_t)b * NSP_PAD * DI; ga.Bl[b] = xpWl + (size_t)b * NSP_PAD * DI;
            ga.bias[b] = xpb[b];
            ga.C[b] = sp + (size_t)b * SL * NSP;
            ga.Dh[b] = dh + (size_t)b * SL * DI;
            ga.rev[b] = 0;
        }
        ga.M = SL; ga.N = NSP; ga.K = DI; ga.ldc = NSP; ga.ldd = DI; ga.dlim = DI;
        k_mma_gemm<0,1><<<dim3(NSP_PAD / 128, SL / 128, 2), 256, GEMM_SMEM>>>(ga);
    }

    // 5. dt-projection + softplus: [2048 x 1024], K=1024
    {
        TArgs ga = {};
        for (int b = 0; b < 2; b++) {
            ga.Ah[b] = dh + (size_t)b * SL * DI;
            ga.Bh[b] = dtWh + (size_t)b * DI * DI; ga.Bl[b] = dtWl + (size_t)b * DI * DI;
            ga.bias[b] = dtb[b];
            ga.C[b] = dtbuf + (size_t)b * SL * DI;
            ga.rev[b] = 0;
        }
        ga.M = SL; ga.N = DI; ga.K = DI; ga.ldc = DI;
        k_mma_gemm<1,0><<<dim3(DI / 128, SL / 128, 2), 256, GEMM_SMEM>>>(ga);
    }

    // 6. chunked selective scan
    k_scanA<<<dim3(DI / 128, NCH, 2), 128>>>(A_log);
    k_scanB<<<(2 * DI * DS + 255) / 256, 256>>>(A_log);
    k_scanC<<<dim3(DI / 128, NCH, 2), 128>>>(A_log, Dp);

    // 7. out-projection: fp16 concat only (bwd rows reversed back)
    {
        TArgs ga = {};
        for (int b = 0; b < 2; b++) {
            ga.Ah[b] = yzh + (size_t)b * SL * DI;
            ga.Bh[b] = outWh + (size_t)b * DM * DI; ga.Bl[b] = outWl + (size_t)b * DM * DI;
            ga.bias[b] = outb[b];
            ga.Dh[b] = cth + b * DM;
            ga.rev[b] = (b == 1);
        }
        ga.M = SL; ga.N = DM; ga.K = DI; ga.ldd = 2 * DM;
        k_mma_gemm<0,2><<<dim3(DM / 128, SL / 128, 2), 256, GEMM_SMEM>>>(ga);
    }

    // 8. fusion: [2048 x 512], K=1024
    {
        TArgs ga = {};
        ga.Ah[0] = ga.Ah[1] = cth;
        ga.Bh[0] = ga.Bh[1] = fuWh; ga.Bl[0] = ga.Bl[1] = fuWl;
        ga.bias[0] = ga.bias[1] = fub;
        ga.C[0] = ga.C[1] = out;
        ga.rev[0] = ga.rev[1] = 0;
        ga.M = SL; ga.N = DM; ga.K = 2 * DM; ga.ldc = DM;
        k_mma_gemm<0,0><<<dim3(DM / 128, SL / 128, 1), 256, GEMM_SMEM>>>(ga);
    }
}

// round 6
// speedup vs baseline: 1.4290x; 1.4290x over previous
#include <cuda_runtime.h>
#include <cuda_fp16.h>
#include <math.h>
#include <stdint.h>

#define SL   2048
#define DM   512
#define DI   1024
#define DS   16
#define DXZ  2048   // 2*DI
#define NSP  1056   // DI + 2*DS
#define NSP_PAD 1152
#define NCH  16
#define CL   128    // SL / NCH
#define WSCALE 64.0f
#define INV_WSCALE 0.015625f

// ---------------- fp32 scratch ----------------
__device__ float g_xz[2 * SL * DXZ];      // in-proj output: x_ssm | z
__device__ float g_xconv[2 * SL * DI];    // post depthwise conv (pre-silu)
__device__ float g_sp[2 * SL * NSP];      // xp-proj output: delta | B | C
__device__ float g_dt[2 * SL * DI];       // softplus(delta @ dtW + dtb)
// scan chunk scratch
__device__ float g_dtsum[2 * DI * NCH];
__device__ float g_hpart[2 * DI * NCH * DS];
__device__ float g_hinit[2 * DI * NCH * DS];

// ---------------- fp16 activations (A operands) ----------------
__device__ __align__(16) __half g_X2h[2 * SL * DM];
__device__ __align__(16) __half g_sxh[2 * SL * DI];
__device__ __align__(16) __half g_dh [2 * SL * DI];
__device__ __align__(16) __half g_yzh[2 * SL * DI];
__device__ __align__(16) __half g_cth[SL * 2 * DM];
// ---------------- fp16 hi/lo transposed scaled weights [Npad][K] ----------------
__device__ __align__(16) __half g_inWh[2 * DXZ * DM],     g_inWl[2 * DXZ * DM];
__device__ __align__(16) __half g_xpWh[2 * NSP_PAD * DI], g_xpWl[2 * NSP_PAD * DI];
__device__ __align__(16) __half g_dtWh[2 * DI * DI],      g_dtWl[2 * DI * DI];
__device__ __align__(16) __half g_outWh[2 * DM * DI],     g_outWl[2 * DM * DI];
__device__ __align__(16) __half g_fuWh[DM * 2 * DM],      g_fuWl[DM * 2 * DM];

// ---------------- helpers ----------------
__device__ __forceinline__ float siluf(float v) { return v / (1.0f + __expf(-v)); }

__device__ __forceinline__ uint32_t smem_u32(const void* p) {
    uint32_t a;
    asm("{ .reg .u64 t; cvta.to.shared.u64 t, %1; cvt.u32.u64 %0, t; }" : "=r"(a) : "l"(p));
    return a;
}
__device__ __forceinline__ void cp16(uint32_t dst, const void* src) {
    asm volatile("cp.async.cg.shared.global [%0], [%1], 16;" :: "r"(dst), "l"(src));
}
__device__ __forceinline__ void cp_commit() {
    asm volatile("cp.async.commit_group;" ::: "memory");
}
__device__ __forceinline__ void cp_wait1() {
    asm volatile("cp.async.wait_group 1;" ::: "memory");
}

#define LDSM_X4(r0, r1, r2, r3, addr) \
    asm volatile("ldmatrix.sync.aligned.m8n8.x4.shared.b16 {%0,%1,%2,%3}, [%4];" \
                 : "=r"(r0), "=r"(r1), "=r"(r2), "=r"(r3) : "r"(addr))

#define MMA16816(d, a, b) \
    asm volatile("mma.sync.aligned.m16n8k16.row.col.f32.f16.f16.f32 " \
                 "{%0,%1,%2,%3}, {%4,%5,%6,%7}, {%8,%9}, {%0,%1,%2,%3};" \
                 : "+f"((d)[0]), "+f"((d)[1]), "+f"((d)[2]), "+f"((d)[3]) \
                 : "r"((a)[0]), "r"((a)[1]), "r"((a)[2]), "r"((a)[3]), \
                   "r"((b)[0]), "r"((b)[1]))

#define SWZ(o) ((o) ^ (((o) >> 3) & 0x70))

// ---------------- prepare: x -> fwd + reversed bwd fp16 ----------------
__global__ void k_prepare(const float* __restrict__ x) {
    int idx = blockIdx.x * blockDim.x + threadIdx.x;
    if (idx < SL * DM) {
        int l = idx / DM, d = idx % DM;
        __half h = __float2half(x[idx]);
        g_X2h[idx] = h;
        g_X2h[(size_t)SL * DM + (size_t)(SL - 1 - l) * DM + d] = h;
    }
}

// ---------------- causal depthwise conv (K=4); fp32 xconv + fp16 silu ----------------
__global__ void k_conv(const float* __restrict__ fcw, const float* __restrict__ fcb,
                       const float* __restrict__ bcw, const float* __restrict__ bcb) {
    int idx = blockIdx.x * blockDim.x + threadIdx.x;
    if (idx >= 2 * SL * DI) return;
    int b = idx / (SL * DI);
    int r = idx - b * SL * DI;
    int l = r / DI, d = r % DI;
    const float* cw = b ? bcw : fcw;
    const float* cb = b ? bcb : fcb;
    const float* xs = g_xz + (size_t)b * SL * DXZ;
    float acc = cb[d];
#pragma unroll
    for (int k = 0; k < 4; k++) {
        int ls = l + k - 3;
        if (ls >= 0) acc += cw[d * 4 + k] * xs[(size_t)ls * DXZ + d];
    }
    g_xconv[idx] = acc;
    g_sxh[idx] = __float2half(siluf(acc));
}

// ---------------- fused weight transpose + scale + hi/lo split (all 9 weights) ----------------
struct WtJobs {
    const float* W[9];
    __half* Bh[9];
    __half* Bl[9];
    int K[9], N[9], bx[9];
    int ofs[10];
};

__global__ void k_wt_all(WtJobs jw) {
    __shared__ float s[32][33];
    int bxg = blockIdx.x;
    int j = 0;
#pragma unroll
    for (int q = 0; q < 9; q++) if (bxg >= jw.ofs[q + 1]) j = q + 1;
    int local = bxg - jw.ofs[j];
    int K = jw.K[j], N = jw.N[j], bxn = jw.bx[j];
    int nb = (local % bxn) * 32, kb = (local / bxn) * 32;
    const float* __restrict__ W = jw.W[j];
    __half* __restrict__ hiT = jw.Bh[j];
    __half* __restrict__ loT = jw.Bl[j];
    int tx = threadIdx.x, ty = threadIdx.y;
#pragma unroll
    for (int q = 0; q < 32; q += 8) {
        int k = kb + ty + q, n = nb + tx;
        s[ty + q][tx] = (n < N) ? W[(size_t)k * N + n] * WSCALE : 0.0f;
    }
    __syncthreads();
#pragma unroll
    for (int q = 0; q < 32; q += 8) {
        int n = nb + ty + q, k = kb + tx;
        float v = s[tx][ty + q];
        __half h = __float2half(v);
        __half l = __float2half(v - __half2float(h));
        hiT[(size_t)n * K + k] = h;
        loT[(size_t)n * K + k] = l;
    }
}

// ---------------- fp16 2-term GEMM: C = A @ (W*64)^T / 64 + bias ----------------
// CTA tile 128x128, K-slab 64, 8 warps (4m x 2n), 2-stage cp.async pipeline (R4 schedule).
struct TArgs {
    const __half *Ah[2], *Bh[2], *Bl[2];
    const float* bias[2];
    float* C[2];
    __half* Dh[2];
    int M, N, K, ldc, ldd, dlim;
    int rev[2];
};

#define TILE_B  16384      // 128 x 64 fp16
#define STAGE_B (3 * TILE_B)
#define GEMM_SMEM (2 * STAGE_B)   // 98304

__device__ __forceinline__ void load_slab(uint32_t sdst,
    const __half* Ah, const __half* Bh, const __half* Bl,
    int m0, int n0, int K, int kslab, int tid)
{
    const __half* srcs[3] = { Ah + (size_t)m0 * K, Bh + (size_t)n0 * K, Bl + (size_t)n0 * K };
    const int kof = kslab * 64;
#pragma unroll
    for (int t = 0; t < 3; t++) {
#pragma unroll
        for (int i = 0; i < 4; i++) {
            int idx = tid + i * 256;
            int r = idx >> 3, c = idx & 7;
            uint32_t dst = sdst + t * TILE_B + SWZ(r * 128 + c * 16);
            cp16(dst, srcs[t] + (size_t)r * K + kof + c * 8);
        }
    }
}

// EPI: 0 none, 1 softplus.  MODE: 0 fp32 C only, 1 fp32 C + fp16 D (cols<dlim), 2 fp16 D only.
template <int EPI, int MODE>
__global__ void __launch_bounds__(256, 1) k_mma_gemm(TArgs ga) {
    extern __shared__ __align__(1024) char smem[];
    const int bz = blockIdx.z;
    const __half* __restrict__ Ah = ga.Ah[bz];
    const __half* __restrict__ Bh = ga.Bh[bz];
    const __half* __restrict__ Bl = ga.Bl[bz];
    const float* __restrict__ bias = ga.bias[bz];
    float* __restrict__ C = ga.C[bz];
    __half* __restrict__ D = ga.Dh[bz];
    const int K = ga.K, N = ga.N, ldc = ga.ldc, ldd = ga.ldd, rev = ga.rev[bz];
    const int m0 = blockIdx.y * 128, n0 = blockIdx.x * 128;

    const int tid = threadIdx.x, wid = tid >> 5, lane = tid & 31;
    const int wm = (wid & 3) * 32;
    const int wn = (wid >> 2) * 64;
    const uint32_t sb = smem_u32(smem);

    float acc[2][8][4];
#pragma unroll
    for (int i = 0; i < 2; i++)
#pragma unroll
        for (int j = 0; j < 8; j++)
#pragma unroll
            for (int q = 0; q < 4; q++) acc[i][j][q] = 0.0f;

    const int nslab = K / 64;

    load_slab(sb, Ah, Bh, Bl, m0, n0, K, 0, tid);
    cp_commit();
    if (nslab > 1) load_slab(sb + STAGE_B, Ah, Bh, Bl, m0, n0, K, 1, tid);
    cp_commit();

    const int a_row = (lane & 15);
    const int a_kc  = (lane >> 4) * 16;
    const int b_row = (lane & 7) + ((lane >> 4) << 3);
    const int b_kc  = ((lane >> 3) & 1) * 16;

    for (int sl = 0; sl < nslab; sl++) {
        cp_wait1();
        __syncthreads();
        const uint32_t st = sb + (sl & 1) * STAGE_B;
        const uint32_t stA = st, stBh = st + TILE_B, stBl = st + 2 * TILE_B;

#pragma unroll
        for (int ks = 0; ks < 4; ks++) {
            uint32_t ah[2][4];
#pragma unroll
            for (int mi = 0; mi < 2; mi++) {
                uint32_t off = SWZ((wm + mi * 16 + a_row) * 128 + ks * 32 + a_kc);
                LDSM_X4(ah[mi][0], ah[mi][1], ah[mi][2], ah[mi][3], stA + off);
            }
            uint32_t bh[8][2], bl[8][2];
#pragma unroll
            for (int jj = 0; jj < 4; jj++) {
                uint32_t off = SWZ((wn + jj * 16 + b_row) * 128 + ks * 32 + b_kc);
                uint32_t r0, r1, r2, r3;
                LDSM_X4(r0, r1, r2, r3, stBh + off);
                bh[jj * 2][0] = r0; bh[jj * 2][1] = r1;
                bh[jj * 2 + 1][0] = r2; bh[jj * 2 + 1][1] = r3;
                LDSM_X4(r0, r1, r2, r3, stBl + off);
                bl[jj * 2][0] = r0; bl[jj * 2][1] = r1;
                bl[jj * 2 + 1][0] = r2; bl[jj * 2 + 1][1] = r3;
            }
#pragma unroll
            for (int mi = 0; mi < 2; mi++)
#pragma unroll
                for (int nj = 0; nj < 8; nj++) {
                    MMA16816(acc[mi][nj], ah[mi], bh[nj]);
                    MMA16816(acc[mi][nj], ah[mi], bl[nj]);
                }
        }
        __syncthreads();
        if (sl + 2 < nslab)
            load_slab(sb + (sl & 1) * STAGE_B, Ah, Bh, Bl, m0, n0, K, sl + 2, tid);
        cp_commit();
    }

    // epilogue
    const int gid = lane >> 2, tig = lane & 3;
#pragma unroll
    for (int mi = 0; mi < 2; mi++) {
        int mb = m0 + wm + mi * 16 + gid;
        int r1 = rev ? (ga.M - 1 - mb) : mb;
        int r2 = rev ? (ga.M - 1 - (mb + 8)) : (mb + 8);
#pragma unroll
        for (int nj = 0; nj < 8; nj++) {
            int nc = n0 + wn + nj * 8 + tig * 2;
            if (nc < N) {
                float b0 = bias[nc], b1 = bias[nc + 1];
                float v0 = acc[mi][nj][0] * INV_WSCALE + b0;
                float v1 = acc[mi][nj][1] * INV_WSCALE + b1;
                float v2 = acc[mi][nj][2] * INV_WSCALE + b0;
                float v3 = acc[mi][nj][3] * INV_WSCALE + b1;
                if (EPI == 1) {
                    v0 = (v0 > 20.0f) ? v0 : log1pf(__expf(v0));
                    v1 = (v1 > 20.0f) ? v1 : log1pf(__expf(v1));
                    v2 = (v2 > 20.0f) ? v2 : log1pf(__expf(v2));
                    v3 = (v3 > 20.0f) ? v3 : log1pf(__expf(v3));
                }
                if (MODE == 0 || MODE == 1) {
                    *(float2*)&C[(size_t)r1 * ldc + nc] = make_float2(v0, v1);
                    *(float2*)&C[(size_t)r2 * ldc + nc] = make_float2(v2, v3);
                }
                if ((MODE == 1 && nc < ga.dlim) || MODE == 2) {
                    *(__half2*)&D[(size_t)r1 * ldd + nc] = __floats2half2_rn(v0, v1);
                    *(__half2*)&D[(size_t)r2 * ldd + nc] = __floats2half2_rn(v2, v3);
                }
            }
        }
    }
}

// ---------------- chunked selective scan ----------------
__global__ void k_scanA(const float* __restrict__ A_log) {
    __shared__ float sB[CL][DS];
    const int b = blockIdx.z, ch = blockIdx.y;
    const int d = blockIdx.x * 128 + threadIdx.x;
    const float* __restrict__ spp = g_sp + (size_t)b * SL * NSP;
    for (int i = threadIdx.x; i < CL * DS; i += 128) {
        int l = i >> 4, s = i & 15;
        sB[l][s] = spp[(size_t)(ch * CL + l) * NSP + DI + s];
    }
    __syncthreads();
    float Ac[DS];
#pragma unroll
    for (int s = 0; s < DS; s++) Ac[s] = -__expf(A_log[d * DS + s]);
    float h[DS];
#pragma unroll
    for (int s = 0; s < DS; s++) h[s] = 0.0f;
    float dts = 0.0f;
    const float* __restrict__ dtp = g_dt + (size_t)b * SL * DI;
    const float* __restrict__ xcp = g_xconv + (size_t)b * SL * DI;
    for (int l = 0; l < CL; l++) {
        int gl = ch * CL + l;
        float dt = dtp[(size_t)gl * DI + d];
        float xv = xcp[(size_t)gl * DI + d];
        dts += dt;
        float du = dt * xv;
#pragma unroll
        for (int s = 0; s < DS; s++) h[s] = __expf(dt * Ac[s]) * h[s] + du * sB[l][s];
    }
    size_t base = ((size_t)(b * DI + d) * NCH + ch) * DS;
#pragma unroll
    for (int s = 0; s < DS; s++) g_hpart[base + s] = h[s];
    g_dtsum[(size_t)(b * DI + d) * NCH + ch] = dts;
}

__global__ void k_scanB(const float* __restrict__ A_log) {
    int idx = blockIdx.x * 256 + threadIdx.x;
    if (idx >= 2 * DI * DS) return;
    int s = idx & 15;
    int d = (idx >> 4) & (DI - 1);
    int b = idx >> 14;
    float Ac = -__expf(A_log[d * DS + s]);
    float h = 0.0f;
    size_t bd = (size_t)(b * DI + d) * NCH;
    for (int ch = 0; ch < NCH; ch++) {
        g_hinit[(bd + ch) * DS + s] = h;
        h = __expf(g_dtsum[bd + ch] * Ac) * h + g_hpart[(bd + ch) * DS + s];
    }
}

__global__ void k_scanC(const float* __restrict__ A_log, const float* __restrict__ Dp) {
    __shared__ float sB[CL][DS];
    __shared__ float sC[CL][DS];
    const int b = blockIdx.z, ch = blockIdx.y;
    const int d = blockIdx.x * 128 + threadIdx.x;
    const float* __restrict__ spp = g_sp + (size_t)b * SL * NSP;
    for (int i = threadIdx.x; i < CL * DS; i += 128) {
        int l = i >> 4, s = i & 15;
        sB[l][s] = spp[(size_t)(ch * CL + l) * NSP + DI + s];
        sC[l][s] = spp[(size_t)(ch * CL + l) * NSP + DI + DS + s];
    }
    __syncthreads();
    float Ac[DS];
#pragma unroll
    for (int s = 0; s < DS; s++) Ac[s] = -__expf(A_log[d * DS + s]);
    float h[DS];
    size_t hbase = ((size_t)(b * DI + d) * NCH + ch) * DS;
#pragma unroll
    for (int s = 0; s < DS; s++) h[s] = g_hinit[hbase + s];
    const float Dv = Dp[d];
    const float* __restrict__ dtp = g_dt + (size_t)b * SL * DI;
    const float* __restrict__ xcp = g_xconv + (size_t)b * SL * DI;
    const float* __restrict__ zp  = g_xz + (size_t)b * SL * DXZ + DI;
    __half* __restrict__ yh = g_yzh + (size_t)b * SL * DI;
    for (int l = 0; l < CL; l++) {
        int gl = ch * CL + l;
        float dt = dtp[(size_t)gl * DI + d];
        float xv = xcp[(size_t)gl * DI + d];
        float du = dt * xv;
        float y = Dv * xv;
#pragma unroll
        for (int s = 0; s < DS; s++) {
            h[s] = __expf(dt * Ac[s]) * h[s] + du * sB[l][s];
            y += h[s] * sC[l][s];
        }
        float zv = zp[(size_t)gl * DXZ + d];
        yh[(size_t)gl * DI + d] = __float2half(y * siluf(zv));
    }
}

// ---------------- host orchestration ----------------
extern "C" void kernel_launch(void* const* d_in, const int* in_sizes, int n_in,
                              void* d_out, int out_size) {
    const float* x = (const float*)d_in[0];
    const float* inW[2]  = {(const float*)d_in[1],  (const float*)d_in[11]};
    const float* inb[2]  = {(const float*)d_in[2],  (const float*)d_in[12]};
    const float* cw[2]   = {(const float*)d_in[3],  (const float*)d_in[13]};
    const float* cb[2]   = {(const float*)d_in[4],  (const float*)d_in[14]};
    const float* xpW[2]  = {(const float*)d_in[5],  (const float*)d_in[15]};
    const float* xpb[2]  = {(const float*)d_in[6],  (const float*)d_in[16]};
    const float* dtW[2]  = {(const float*)d_in[7],  (const float*)d_in[17]};
    const float* dtb[2]  = {(const float*)d_in[8],  (const float*)d_in[18]};
    const float* outW[2] = {(const float*)d_in[9],  (const float*)d_in[19]};
    const float* outb[2] = {(const float*)d_in[10], (const float*)d_in[20]};
    const float* A_log   = (const float*)d_in[21];
    const float* Dp      = (const float*)d_in[22];
    const float* fuW     = (const float*)d_in[23];
    const float* fub     = (const float*)d_in[24];
    float* out = (float*)d_out;

    cudaFuncSetAttribute(k_mma_gemm<0,0>, cudaFuncAttributeMaxDynamicSharedMemorySize, GEMM_SMEM);
    cudaFuncSetAttribute(k_mma_gemm<0,1>, cudaFuncAttributeMaxDynamicSharedMemorySize, GEMM_SMEM);
    cudaFuncSetAttribute(k_mma_gemm<0,2>, cudaFuncAttributeMaxDynamicSharedMemorySize, GEMM_SMEM);
    cudaFuncSetAttribute(k_mma_gemm<1,0>, cudaFuncAttributeMaxDynamicSharedMemorySize, GEMM_SMEM);

    float *xz, *sp, *dtbuf;
    __half *X2h, *sxh, *dh, *yzh, *cth;
    __half *inWh, *inWl, *xpWh, *xpWl, *dtWh, *dtWl, *outWh, *outWl, *fuWh, *fuWl;
    cudaGetSymbolAddress((void**)&xz, g_xz);
    cudaGetSymbolAddress((void**)&sp, g_sp);
    cudaGetSymbolAddress((void**)&dtbuf, g_dt);
    cudaGetSymbolAddress((void**)&X2h, g_X2h);
    cudaGetSymbolAddress((void**)&sxh, g_sxh);
    cudaGetSymbolAddress((void**)&dh, g_dh);
    cudaGetSymbolAddress((void**)&yzh, g_yzh);
    cudaGetSymbolAddress((void**)&cth, g_cth);
    cudaGetSymbolAddress((void**)&inWh, g_inWh);   cudaGetSymbolAddress((void**)&inWl, g_inWl);
    cudaGetSymbolAddress((void**)&xpWh, g_xpWh);   cudaGetSymbolAddress((void**)&xpWl, g_xpWl);
    cudaGetSymbolAddress((void**)&dtWh, g_dtWh);   cudaGetSymbolAddress((void**)&dtWl, g_dtWl);
    cudaGetSymbolAddress((void**)&outWh, g_outWh); cudaGetSymbolAddress((void**)&outWl, g_outWl);
    cudaGetSymbolAddress((void**)&fuWh, g_fuWh);   cudaGetSymbolAddress((void**)&fuWl, g_fuWl);

    // 0. fused weight transpose + scale + split (9 jobs, 1 launch)
    {
        WtJobs jw;
        const float* Ws[9] = {inW[0], inW[1], xpW[0], xpW[1], dtW[0], dtW[1], outW[0], outW[1], fuW};
        __half* Hs[9] = {inWh, inWh + (size_t)DXZ * DM, xpWh, xpWh + (size_t)NSP_PAD * DI,
                         dtWh, dtWh + (size_t)DI * DI, outWh, outWh + (size_t)DM * DI, fuWh};
        __half* Ls[9] = {inWl, inWl + (size_t)DXZ * DM, xpWl, xpWl + (size_t)NSP_PAD * DI,
                         dtWl, dtWl + (size_t)DI * DI, outWl, outWl + (size_t)DM * DI, fuWl};
        int Ks[9]  = {DM, DM, DI, DI, DI, DI, DI, DI, 2 * DM};
        int Ns[9]  = {DXZ, DXZ, NSP, NSP, DI, DI, DM, DM, DM};
        int Nps[9] = {DXZ, DXZ, NSP_PAD, NSP_PAD, DI, DI, DM, DM, DM};
        int ofs = 0;
        jw.ofs[0] = 0;
        for (int j = 0; j < 9; j++) {
            jw.W[j] = Ws[j]; jw.Bh[j] = Hs[j]; jw.Bl[j] = Ls[j];
            jw.K[j] = Ks[j]; jw.N[j] = Ns[j]; jw.bx[j] = Nps[j] / 32;
            ofs += (Nps[j] / 32) * (Ks[j] / 32);
            jw.ofs[j + 1] = ofs;
        }
        k_wt_all<<<ofs, dim3(32, 8)>>>(jw);
    }

    // 1. prepare inputs
    k_prepare<<<(SL * DM + 255) / 256, 256>>>(x);

    // 2. in-projection: [2048 x 2048], K=512
    {
        TArgs ga = {};
        for (int b = 0; b < 2; b++) {
            ga.Ah[b] = X2h + (size_t)b * SL * DM;
            ga.Bh[b] = inWh + (size_t)b * DXZ * DM; ga.Bl[b] = inWl + (size_t)b * DXZ * DM;
            ga.bias[b] = inb[b];
            ga.C[b] = xz + (size_t)b * SL * DXZ;
            ga.rev[b] = 0;
        }
        ga.M = SL; ga.N = DXZ; ga.K = DM; ga.ldc = DXZ;
        k_mma_gemm<0,0><<<dim3(DXZ / 128, SL / 128, 2), 256, GEMM_SMEM>>>(ga);
    }

    // 3. depthwise conv + silu (fp16 out)
    k_conv<<<(2 * SL * DI + 255) / 256, 256>>>(cw[0], cb[0], cw[1], cb[1]);

    // 4. xp-projection: fp32 sp + fused fp16 delta split
    {
        TArgs ga = {};
        for (int b = 0; b < 2; b++) {
            ga.Ah[b] = sxh + (size_t)b * SL * DI;
            ga.Bh[b] = xpWh + (size_t)b * NSP_PAD * DI; ga.Bl[b] = xpWl + (size_t)b * NSP_PAD * DI;
            ga.bias[b] = xpb[b];
            ga.C[b] = sp + (size_t)b * SL * NSP;
            ga.Dh[b] = dh + (size_t)b * SL * DI;
            ga.rev[b] = 0;
        }
        ga.M = SL; ga.N = NSP; ga.K = DI; ga.ldc = NSP; ga.ldd = DI; ga.dlim = DI;
        k_mma_gemm<0,1><<<dim3(NSP_PAD / 128, SL / 128, 2), 256, GEMM_SMEM>>>(ga);
    }

    // 5. dt-projection + softplus: [2048 x 1024], K=1024
    {
        TArgs ga = {};
        for (int b = 0; b < 2; b++) {
            ga.Ah[b] = dh + (size_t)b * SL * DI;
            ga.Bh[b] = dtWh + (size_t)b * DI * DI; ga.Bl[b] = dtWl + (size_t)b * DI * DI;
            ga.bias[b] = dtb[b];
            ga.C[b] = dtbuf + (size_t)b * SL * DI;
            ga.rev[b] = 0;
        }
        ga.M = SL; ga.N = DI; ga.K = DI; ga.ldc = DI;
        k_mma_gemm<1,0><<<dim3(DI / 128, SL / 128, 2), 256, GEMM_SMEM>>>(ga);
    }

    // 6. chunked selective scan
    k_scanA<<<dim3(DI / 128, NCH, 2), 128>>>(A_log);
    k_scanB<<<(2 * DI * DS + 255) / 256, 256>>>(A_log);
    k_scanC<<<dim3(DI / 128, NCH, 2), 128>>>(A_log, Dp);

    // 7. out-projection: fp16 concat only (bwd rows reversed back)
    {
        TArgs ga = {};
        for (int b = 0; b < 2; b++) {
            ga.Ah[b] = yzh + (size_t)b * SL * DI;
            ga.Bh[b] = outWh + (size_t)b * DM * DI; ga.Bl[b] = outWl + (size_t)b * DM * DI;
            ga.bias[b] = outb[b];
            ga.Dh[b] = cth + b * DM;
            ga.rev[b] = (b == 1);
        }
        ga.M = SL; ga.N = DM; ga.K = DI; ga.ldd = 2 * DM;
        k_mma_gemm<0,2><<<dim3(DM / 128, SL / 128, 2), 256, GEMM_SMEM>>>(ga);
    }

    // 8. fusion: [2048 x 512], K=1024
    {
        TArgs ga = {};
        ga.Ah[0] = ga.Ah[1] = cth;
        ga.Bh[0] = ga.Bh[1] = fuWh; ga.Bl[0] = ga.Bl[1] = fuWl;
        ga.bias[0] = ga.bias[1] = fub;
        ga.C[0] = ga.C[1] = out;
        ga.rev[0] = ga.rev[1] = 0;
        ga.M = SL; ga.N = DM; ga.K = 2 * DM; ga.ldc = DM;
        k_mma_gemm<0,0><<<dim3(DM / 128, SL / 128, 1), 256, GEMM_SMEM>>>(ga);
    }
}

// round 10
// speedup vs baseline: 1.4444x; 1.0108x over previous
#include <cuda_runtime.h>
#include <cuda_fp16.h>
#include <math.h>
#include <stdint.h>

#define SL   2048
#define DM   512
#define DI   1024
#define DS   16
#define DXZ  2048   // 2*DI
#define NSP  1056   // DI + 2*DS
#define NSP_PAD 1152
#define NCH  16
#define CL   128    // SL / NCH
#define WSCALE 64.0f
#define INV_WSCALE 0.015625f

// ---------------- fp32 scratch ----------------
__device__ float g_xz[2 * SL * DXZ];      // in-proj output: x_ssm | z
__device__ float g_xconv[2 * SL * DI];    // post depthwise conv (pre-silu)
__device__ float g_sp[2 * SL * NSP];      // xp-proj output: delta | B | C
__device__ float g_dt[2 * SL * DI];       // softplus(delta @ dtW + dtb)
// scan chunk scratch
__device__ float g_dtsum[2 * DI * NCH];
__device__ float g_hpart[2 * DI * NCH * DS];
__device__ float g_hinit[2 * DI * NCH * DS];

// ---------------- fp16 activations (A operands) ----------------
__device__ __align__(16) __half g_X2h[2 * SL * DM];
__device__ __align__(16) __half g_sxh[2 * SL * DI];
__device__ __align__(16) __half g_dh [2 * SL * DI];
__device__ __align__(16) __half g_yzh[2 * SL * DI];
__device__ __align__(16) __half g_cth[SL * 2 * DM];
// ---------------- fp16 hi/lo transposed scaled weights [Npad][K] ----------------
__device__ __align__(16) __half g_inWh[2 * DXZ * DM],     g_inWl[2 * DXZ * DM];
__device__ __align__(16) __half g_xpWh[2 * NSP_PAD * DI], g_xpWl[2 * NSP_PAD * DI];
__device__ __align__(16) __half g_dtWh[2 * DI * DI],      g_dtWl[2 * DI * DI];
__device__ __align__(16) __half g_outWh[2 * DM * DI],     g_outWl[2 * DM * DI];
__device__ __align__(16) __half g_fuWh[DM * 2 * DM],      g_fuWl[DM * 2 * DM];

// ---------------- helpers ----------------
__device__ __forceinline__ float siluf(float v) { return v / (1.0f + __expf(-v)); }

__device__ __forceinline__ uint32_t smem_u32(const void* p) {
    uint32_t a;
    asm("{ .reg .u64 t; cvta.to.shared.u64 t, %1; cvt.u32.u64 %0, t; }" : "=r"(a) : "l"(p));
    return a;
}
__device__ __forceinline__ void cp16(uint32_t dst, const void* src) {
    asm volatile("cp.async.cg.shared.global [%0], [%1], 16;" :: "r"(dst), "l"(src));
}
__device__ __forceinline__ void cp_commit() {
    asm volatile("cp.async.commit_group;" ::: "memory");
}
__device__ __forceinline__ void cp_wait1() {
    asm volatile("cp.async.wait_group 1;" ::: "memory");
}

#define LDSM_X4(r0, r1, r2, r3, addr) \
    asm volatile("ldmatrix.sync.aligned.m8n8.x4.shared.b16 {%0,%1,%2,%3}, [%4];" \
                 : "=r"(r0), "=r"(r1), "=r"(r2), "=r"(r3) : "r"(addr))

#define MMA16816(d, a, b) \
    asm volatile("mma.sync.aligned.m16n8k16.row.col.f32.f16.f16.f32 " \
                 "{%0,%1,%2,%3}, {%4,%5,%6,%7}, {%8,%9}, {%0,%1,%2,%3};" \
                 : "+f"((d)[0]), "+f"((d)[1]), "+f"((d)[2]), "+f"((d)[3]) \
                 : "r"((a)[0]), "r"((a)[1]), "r"((a)[2]), "r"((a)[3]), \
                   "r"((b)[0]), "r"((b)[1]))

#define SWZ(o) ((o) ^ (((o) >> 3) & 0x70))

// ---------------- prepare: x -> fwd + reversed bwd fp16 ----------------
__global__ void k_prepare(const float* __restrict__ x) {
    int idx = blockIdx.x * blockDim.x + threadIdx.x;
    if (idx < SL * DM) {
        int l = idx / DM, d = idx % DM;
        __half h = __float2half(x[idx]);
        g_X2h[idx] = h;
        g_X2h[(size_t)SL * DM + (size_t)(SL - 1 - l) * DM + d] = h;
    }
}

// ---------------- causal depthwise conv (K=4); fp32 xconv + fp16 silu ----------------
__global__ void k_conv(const float* __restrict__ fcw, const float* __restrict__ fcb,
                       const float* __restrict__ bcw, const float* __restrict__ bcb) {
    int idx = blockIdx.x * blockDim.x + threadIdx.x;
    if (idx >= 2 * SL * DI) return;
    int b = idx / (SL * DI);
    int r = idx - b * SL * DI;
    int l = r / DI, d = r % DI;
    const float* cw = b ? bcw : fcw;
    const float* cb = b ? bcb : fcb;
    const float* xs = g_xz + (size_t)b * SL * DXZ;
    float acc = cb[d];
#pragma unroll
    for (int k = 0; k < 4; k++) {
        int ls = l + k - 3;
        if (ls >= 0) acc += cw[d * 4 + k] * xs[(size_t)ls * DXZ + d];
    }
    g_xconv[idx] = acc;
    g_sxh[idx] = __float2half(siluf(acc));
}

// ---------------- fused weight transpose + scale + hi/lo split (all 9 weights) ----------------
struct WtJobs {
    const float* W[9];
    __half* Bh[9];
    __half* Bl[9];
    int K[9], N[9], bx[9];
    int ofs[10];
};

__global__ void k_wt_all(WtJobs jw) {
    __shared__ float s[32][33];
    int bxg = blockIdx.x;
    int j = 0;
#pragma unroll
    for (int q = 0; q < 9; q++) if (bxg >= jw.ofs[q + 1]) j = q + 1;
    int local = bxg - jw.ofs[j];
    int K = jw.K[j], N = jw.N[j], bxn = jw.bx[j];
    int nb = (local % bxn) * 32, kb = (local / bxn) * 32;
    const float* __restrict__ W = jw.W[j];
    __half* __restrict__ hiT = jw.Bh[j];
    __half* __restrict__ loT = jw.Bl[j];
    int tx = threadIdx.x, ty = threadIdx.y;
#pragma unroll
    for (int q = 0; q < 32; q += 8) {
        int k = kb + ty + q, n = nb + tx;
        s[ty + q][tx] = (n < N) ? W[(size_t)k * N + n] * WSCALE : 0.0f;
    }
    __syncthreads();
#pragma unroll
    for (int q = 0; q < 32; q += 8) {
        int n = nb + ty + q, k = kb + tx;
        float v = s[tx][ty + q];
        __half h = __float2half(v);
        __half l = __float2half(v - __half2float(h));
        hiT[(size_t)n * K + k] = h;
        loT[(size_t)n * K + k] = l;
    }
}

// ---------------- fp16 2-term GEMM: C = A @ (W*64)^T / 64 + bias ----------------
// Template BM: CTA tile BM x 128, K-slab 64, 8 warps, 2-stage cp.async pipeline.
// BM=128: warp tile 32x64 (proven R6 shape). BM=256: warp tile 64x64 (higher reuse).
struct TArgs {
    const __half *Ah[2], *Bh[2], *Bl[2];
    const float* bias[2];
    float* C[2];
    __half* Dh[2];
    int M, N, K, ldc, ldd, dlim;
    int rev[2];
};

#define BTILE_B 16384      // 128 x 64 fp16 (B hi or lo tile)

// EPI: 0 none, 1 softplus.  MODE: 0 fp32 C, 1 fp32 C + fp16 D (cols<dlim), 2 fp16 D only.
template <int EPI, int MODE, int BM>
__global__ void __launch_bounds__(256, 1) k_mma_gemm(TArgs ga) {
    constexpr int MI = BM / 64;              // m microtiles per warp (2 or 4)
    constexpr int TILE_A = BM * 128;         // A tile bytes
    constexpr int STG = TILE_A + 2 * BTILE_B;
    extern __shared__ __align__(1024) char smem[];
    const int bz = blockIdx.z;
    const __half* __restrict__ Ah = ga.Ah[bz];
    const __half* __restrict__ Bh = ga.Bh[bz];
    const __half* __restrict__ Bl = ga.Bl[bz];
    const float* __restrict__ bias = ga.bias[bz];
    float* __restrict__ C = ga.C[bz];
    __half* __restrict__ D = ga.Dh[bz];
    const int K = ga.K, N = ga.N, ldc = ga.ldc, ldd = ga.ldd, rev = ga.rev[bz];
    const int m0 = blockIdx.y * BM, n0 = blockIdx.x * 128;

    const int tid = threadIdx.x, wid = tid >> 5, lane = tid & 31;
    const int wm = (wid & 3) * (16 * MI);
    const int wn = (wid >> 2) * 64;
    const uint32_t sb = smem_u32(smem);

    float acc[MI][8][4];
#pragma unroll
    for (int i = 0; i < MI; i++)
#pragma unroll
        for (int j = 0; j < 8; j++)
#pragma unroll
            for (int q = 0; q < 4; q++) acc[i][j][q] = 0.0f;

    const int nslab = K / 64;
    const __half* Abase = Ah + (size_t)m0 * K;
    const __half* Bhb = Bh + (size_t)n0 * K;
    const __half* Blb = Bl + (size_t)n0 * K;

    auto load_slab = [&](uint32_t sdst, int kslab) {
        const int kof = kslab * 64;
#pragma unroll
        for (int i = 0; i < BM / 32; i++) {
            int idx = tid + i * 256;
            int r = idx >> 3, c = idx & 7;
            cp16(sdst + SWZ(r * 128 + c * 16), Abase + (size_t)r * K + kof + c * 8);
        }
#pragma unroll
        for (int i = 0; i < 4; i++) {
            int idx = tid + i * 256;
            int r = idx >> 3, c = idx & 7;
            uint32_t so = SWZ(r * 128 + c * 16);
            cp16(sdst + TILE_A + so, Bhb + (size_t)r * K + kof + c * 8);
            cp16(sdst + TILE_A + BTILE_B + so, Blb + (size_t)r * K + kof + c * 8);
        }
    };

    load_slab(sb, 0);
    cp_commit();
    if (nslab > 1) load_slab(sb + STG, 1);
    cp_commit();

    const int a_row = (lane & 15);
    const int a_kc  = (lane >> 4) * 16;
    const int b_row = (lane & 7) + ((lane >> 4) << 3);
    const int b_kc  = ((lane >> 3) & 1) * 16;

    for (int sl = 0; sl < nslab; sl++) {
        cp_wait1();
        __syncthreads();
        const uint32_t st = sb + (sl & 1) * STG;
        const uint32_t stA = st, stBh = st + TILE_A, stBl = st + TILE_A + BTILE_B;

#pragma unroll
        for (int ks = 0; ks < 4; ks++) {
            uint32_t ah[MI][4];
#pragma unroll
            for (int mi = 0; mi < MI; mi++) {
                uint32_t off = SWZ((wm + mi * 16 + a_row) * 128 + ks * 32 + a_kc);
                LDSM_X4(ah[mi][0], ah[mi][1], ah[mi][2], ah[mi][3], stA + off);
            }
            uint32_t bh[8][2], bl[8][2];
#pragma unroll
            for (int jj = 0; jj < 4; jj++) {
                uint32_t off = SWZ((wn + jj * 16 + b_row) * 128 + ks * 32 + b_kc);
                uint32_t r0, r1, r2, r3;
                LDSM_X4(r0, r1, r2, r3, stBh + off);
                bh[jj * 2][0] = r0; bh[jj * 2][1] = r1;
                bh[jj * 2 + 1][0] = r2; bh[jj * 2 + 1][1] = r3;
                LDSM_X4(r0, r1, r2, r3, stBl + off);
                bl[jj * 2][0] = r0; bl[jj * 2][1] = r1;
                bl[jj * 2 + 1][0] = r2; bl[jj * 2 + 1][1] = r3;
            }
#pragma unroll
            for (int mi = 0; mi < MI; mi++)
#pragma unroll
                for (int nj = 0; nj < 8; nj++) {
                    MMA16816(acc[mi][nj], ah[mi], bh[nj]);
                    MMA16816(acc[mi][nj], ah[mi], bl[nj]);
                }
        }
        __syncthreads();
        if (sl + 2 < nslab) load_slab(sb + (sl & 1) * STG, sl + 2);
        cp_commit();
    }

    // epilogue
    const int gid = lane >> 2, tig = lane & 3;
#pragma unroll
    for (int mi = 0; mi < MI; mi++) {
        int mb = m0 + wm + mi * 16 + gid;
        int r1 = rev ? (ga.M - 1 - mb) : mb;
        int r2 = rev ? (ga.M - 1 - (mb + 8)) : (mb + 8);
#pragma unroll
        for (int nj = 0; nj < 8; nj++) {
            int nc = n0 + wn + nj * 8 + tig * 2;
            if (nc < N) {
                float b0 = bias[nc], b1 = bias[nc + 1];
                float v0 = acc[mi][nj][0] * INV_WSCALE + b0;
                float v1 = acc[mi][nj][1] * INV_WSCALE + b1;
                float v2 = acc[mi][nj][2] * INV_WSCALE + b0;
                float v3 = acc[mi][nj][3] * INV_WSCALE + b1;
                if (EPI == 1) {
                    v0 = (v0 > 20.0f) ? v0 : log1pf(__expf(v0));
                    v1 = (v1 > 20.0f) ? v1 : log1pf(__expf(v1));
                    v2 = (v2 > 20.0f) ? v2 : log1pf(__expf(v2));
                    v3 = (v3 > 20.0f) ? v3 : log1pf(__expf(v3));
                }
                if (MODE == 0 || MODE == 1) {
                    *(float2*)&C[(size_t)r1 * ldc + nc] = make_float2(v0, v1);
                    *(float2*)&C[(size_t)r2 * ldc + nc] = make_float2(v2, v3);
                }
                if ((MODE == 1 && nc < ga.dlim) || MODE == 2) {
                    *(__half2*)&D[(size_t)r1 * ldd + nc] = __floats2half2_rn(v0, v1);
                    *(__half2*)&D[(size_t)r2 * ldd + nc] = __floats2half2_rn(v2, v3);
                }
            }
        }
    }
}

#define SMEM128 (2 * (128 * 128 + 2 * BTILE_B))   //  98304
#define SMEM256 (2 * (256 * 128 + 2 * BTILE_B))   // 131072

// ---------------- chunked selective scan ----------------
__global__ void k_scanA(const float* __restrict__ A_log) {
    __shared__ float sB[CL][DS];
    const int b = blockIdx.z, ch = blockIdx.y;
    const int d = blockIdx.x * 128 + threadIdx.x;
    const float* __restrict__ spp = g_sp + (size_t)b * SL * NSP;
    for (int i = threadIdx.x; i < CL * DS; i += 128) {
        int l = i >> 4, s = i & 15;
        sB[l][s] = spp[(size_t)(ch * CL + l) * NSP + DI + s];
    }
    __syncthreads();
    float Ac[DS];
#pragma unroll
    for (int s = 0; s < DS; s++) Ac[s] = -__expf(A_log[d * DS + s]);
    float h[DS];
#pragma unroll
    for (int s = 0; s < DS; s++) h[s] = 0.0f;
    float dts = 0.0f;
    const float* __restrict__ dtp = g_dt + (size_t)b * SL * DI;
    const float* __restrict__ xcp = g_xconv + (size_t)b * SL * DI;
    for (int l = 0; l < CL; l++) {
        int gl = ch * CL + l;
        float dt = dtp[(size_t)gl * DI + d];
        float xv = xcp[(size_t)gl * DI + d];
        dts += dt;
        float du = dt * xv;
#pragma unroll
        for (int s = 0; s < DS; s++) h[s] = __expf(dt * Ac[s]) * h[s] + du * sB[l][s];
    }
    size_t base = ((size_t)(b * DI + d) * NCH + ch) * DS;
#pragma unroll
    for (int s = 0; s < DS; s++) g_hpart[base + s] = h[s];
    g_dtsum[(size_t)(b * DI + d) * NCH + ch] = dts;
}

__global__ void k_scanB(const float* __restrict__ A_log) {
    int idx = blockIdx.x * 256 + threadIdx.x;
    if (idx >= 2 * DI * DS) return;
    int s = idx & 15;
    int d = (idx >> 4) & (DI - 1);
    int b = idx >> 14;
    float Ac = -__expf(A_log[d * DS + s]);
    float h = 0.0f;
    size_t bd = (size_t)(b * DI + d) * NCH;
    for (int ch = 0; ch < NCH; ch++) {
        g_hinit[(bd + ch) * DS + s] = h;
        h = __expf(g_dtsum[bd + ch] * Ac) * h + g_hpart[(bd + ch) * DS + s];
    }
}

__global__ void k_scanC(const float* __restrict__ A_log, const float* __restrict__ Dp) {
    __shared__ float sB[CL][DS];
    __shared__ float sC[CL][DS];
    const int b = blockIdx.z, ch = blockIdx.y;
    const int d = blockIdx.x * 128 + threadIdx.x;
    const float* __restrict__ spp = g_sp + (size_t)b * SL * NSP;
    for (int i = threadIdx.x; i < CL * DS; i += 128) {
        int l = i >> 4, s = i & 15;
        sB[l][s] = spp[(size_t)(ch * CL + l) * NSP + DI + s];
        sC[l][s] = spp[(size_t)(ch * CL + l) * NSP + DI + DS + s];
    }
    __syncthreads();
    float Ac[DS];
#pragma unroll
    for (int s = 0; s < DS; s++) Ac[s] = -__expf(A_log[d * DS + s]);
    float h[DS];
    size_t hbase = ((size_t)(b * DI + d) * NCH + ch) * DS;
#pragma unroll
    for (int s = 0; s < DS; s++) h[s] = g_hinit[hbase + s];
    const float Dv = Dp[d];
    const float* __restrict__ dtp = g_dt + (size_t)b * SL * DI;
    const float* __restrict__ xcp = g_xconv + (size_t)b * SL * DI;
    const float* __restrict__ zp  = g_xz + (size_t)b * SL * DXZ + DI;
    __half* __restrict__ yh = g_yzh + (size_t)b * SL * DI;
    for (int l = 0; l < CL; l++) {
        int gl = ch * CL + l;
        float dt = dtp[(size_t)gl * DI + d];
        float xv = xcp[(size_t)gl * DI + d];
        float du = dt * xv;
        float y = Dv * xv;
#pragma unroll
        for (int s = 0; s < DS; s++) {
            h[s] = __expf(dt * Ac[s]) * h[s] + du * sB[l][s];
            y += h[s] * sC[l][s];
        }
        float zv = zp[(size_t)gl * DXZ + d];
        yh[(size_t)gl * DI + d] = __float2half(y * siluf(zv));
    }
}

// ---------------- host orchestration ----------------
extern "C" void kernel_launch(void* const* d_in, const int* in_sizes, int n_in,
                              void* d_out, int out_size) {
    const float* x = (const float*)d_in[0];
    const float* inW[2]  = {(const float*)d_in[1],  (const float*)d_in[11]};
    const float* inb[2]  = {(const float*)d_in[2],  (const float*)d_in[12]};
    const float* cw[2]   = {(const float*)d_in[3],  (const float*)d_in[13]};
    const float* cb[2]   = {(const float*)d_in[4],  (const float*)d_in[14]};
    const float* xpW[2]  = {(const float*)d_in[5],  (const float*)d_in[15]};
    const float* xpb[2]  = {(const float*)d_in[6],  (const float*)d_in[16]};
    const float* dtW[2]  = {(const float*)d_in[7],  (const float*)d_in[17]};
    const float* dtb[2]  = {(const float*)d_in[8],  (const float*)d_in[18]};
    const float* outW[2] = {(const float*)d_in[9],  (const float*)d_in[19]};
    const float* outb[2] = {(const float*)d_in[10], (const float*)d_in[20]};
    const float* A_log   = (const float*)d_in[21];
    const float* Dp      = (const float*)d_in[22];
    const float* fuW     = (const float*)d_in[23];
    const float* fub     = (const float*)d_in[24];
    float* out = (float*)d_out;

    cudaFuncSetAttribute(k_mma_gemm<0,0,256>, cudaFuncAttributeMaxDynamicSharedMemorySize, SMEM256);
    cudaFuncSetAttribute(k_mma_gemm<0,1,256>, cudaFuncAttributeMaxDynamicSharedMemorySize, SMEM256);
    cudaFuncSetAttribute(k_mma_gemm<1,0,256>, cudaFuncAttributeMaxDynamicSharedMemorySize, SMEM256);
    cudaFuncSetAttribute(k_mma_gemm<0,2,128>, cudaFuncAttributeMaxDynamicSharedMemorySize, SMEM128);
    cudaFuncSetAttribute(k_mma_gemm<0,0,128>, cudaFuncAttributeMaxDynamicSharedMemorySize, SMEM128);

    float *xz, *sp, *dtbuf;
    __half *X2h, *sxh, *dh, *yzh, *cth;
    __half *inWh, *inWl, *xpWh, *xpWl, *dtWh, *dtWl, *outWh, *outWl, *fuWh, *fuWl;
    cudaGetSymbolAddress((void**)&xz, g_xz);
    cudaGetSymbolAddress((void**)&sp, g_sp);
    cudaGetSymbolAddress((void**)&dtbuf, g_dt);
    cudaGetSymbolAddress((void**)&X2h, g_X2h);
    cudaGetSymbolAddress((void**)&sxh, g_sxh);
    cudaGetSymbolAddress((void**)&dh, g_dh);
    cudaGetSymbolAddress((void**)&yzh, g_yzh);
    cudaGetSymbolAddress((void**)&cth, g_cth);
    cudaGetSymbolAddress((void**)&inWh, g_inWh);   cudaGetSymbolAddress((void**)&inWl, g_inWl);
    cudaGetSymbolAddress((void**)&xpWh, g_xpWh);   cudaGetSymbolAddress((void**)&xpWl, g_xpWl);
    cudaGetSymbolAddress((void**)&dtWh, g_dtWh);   cudaGetSymbolAddress((void**)&dtWl, g_dtWl);
    cudaGetSymbolAddress((void**)&outWh, g_outWh); cudaGetSymbolAddress((void**)&outWl, g_outWl);
    cudaGetSymbolAddress((void**)&fuWh, g_fuWh);   cudaGetSymbolAddress((void**)&fuWl, g_fuWl);

    // 0. fused weight transpose + scale + split (9 jobs, 1 launch)
    {
        WtJobs jw;
        const float* Ws[9] = {inW[0], inW[1], xpW[0], xpW[1], dtW[0], dtW[1], outW[0], outW[1], fuW};
        __half* Hs[9] = {inWh, inWh + (size_t)DXZ * DM, xpWh, xpWh + (size_t)NSP_PAD * DI,
                         dtWh, dtWh + (size_t)DI * DI, outWh, outWh + (size_t)DM * DI, fuWh};
        __half* Ls[9] = {inWl, inWl + (size_t)DXZ * DM, xpWl, xpWl + (size_t)NSP_PAD * DI,
                         dtWl, dtWl + (size_t)DI * DI, outWl, outWl + (size_t)DM * DI, fuWl};
        int Ks[9]  = {DM, DM, DI, DI, DI, DI, DI, DI, 2 * DM};
        int Ns[9]  = {DXZ, DXZ, NSP, NSP, DI, DI, DM, DM, DM};
        int Nps[9] = {DXZ, DXZ, NSP_PAD, NSP_PAD, DI, DI, DM, DM, DM};
        int ofs = 0;
        jw.ofs[0] = 0;
        for (int j = 0; j < 9; j++) {
            jw.W[j] = Ws[j]; jw.Bh[j] = Hs[j]; jw.Bl[j] = Ls[j];
            jw.K[j] = Ks[j]; jw.N[j] = Ns[j]; jw.bx[j] = Nps[j] / 32;
            ofs += (Nps[j] / 32) * (Ks[j] / 32);
            jw.ofs[j + 1] = ofs;
        }
        k_wt_all<<<ofs, dim3(32, 8)>>>(jw);
    }

    // 1. prepare inputs
    k_prepare<<<(SL * DM + 255) / 256, 256>>>(x);

    // 2. in-projection: [2048 x 2048], K=512  (BM=256)
    {
        TArgs ga = {};
        for (int b = 0; b < 2; b++) {
            ga.Ah[b] = X2h + (size_t)b * SL * DM;
            ga.Bh[b] = inWh + (size_t)b * DXZ * DM; ga.Bl[b] = inWl + (size_t)b * DXZ * DM;
            ga.bias[b] = inb[b];
            ga.C[b] = xz + (size_t)b * SL * DXZ;
            ga.rev[b] = 0;
        }
        ga.M = SL; ga.N = DXZ; ga.K = DM; ga.ldc = DXZ;
        k_mma_gemm<0,0,256><<<dim3(DXZ / 128, SL / 256, 2), 256, SMEM256>>>(ga);
    }

    // 3. depthwise conv + silu (fp16 out)
    k_conv<<<(2 * SL * DI + 255) / 256, 256>>>(cw[0], cb[0], cw[1], cb[1]);

    // 4. xp-projection: fp32 sp + fused fp16 delta split  (BM=256)
    {
        TArgs ga = {};
        for (int b = 0; b < 2; b++) {
            ga.Ah[b] = sxh + (size_t)b * SL * DI;
            ga.Bh[b] = xpWh + (size_t)b * NSP_PAD * DI; ga.Bl[b] = xpWl + (size_t)b * NSP_PAD * DI;
            ga.bias[b] = xpb[b];
            ga.C[b] = sp + (size_t)b * SL * NSP;
            ga.Dh[b] = dh + (size_t)b * SL * DI;
            ga.rev[b] = 0;
        }
        ga.M = SL; ga.N = NSP; ga.K = DI; ga.ldc = NSP; ga.ldd = DI; ga.dlim = DI;
        k_mma_gemm<0,1,256><<<dim3(NSP_PAD / 128, SL / 256, 2), 256, SMEM256>>>(ga);
    }

    // 5. dt-projection + softplus: [2048 x 1024], K=1024  (BM=256)
    {
        TArgs ga = {};
        for (int b = 0; b < 2; b++) {
            ga.Ah[b] = dh + (size_t)b * SL * DI;
            ga.Bh[b] = dtWh + (size_t)b * DI * DI; ga.Bl[b] = dtWl + (size_t)b * DI * DI;
            ga.bias[b] = dtb[b];
            ga.C[b] = dtbuf + (size_t)b * SL * DI;
            ga.rev[b] = 0;
        }
        ga.M = SL; ga.N = DI; ga.K = DI; ga.ldc = DI;
        k_mma_gemm<1,0,256><<<dim3(DI / 128, SL / 256, 2), 256, SMEM256>>>(ga);
    }

    // 6. chunked selective scan
    k_scanA<<<dim3(DI / 128, NCH, 2), 128>>>(A_log);
    k_scanB<<<(2 * DI * DS + 255) / 256, 256>>>(A_log);
    k_scanC<<<dim3(DI / 128, NCH, 2), 128>>>(A_log, Dp);

    // 7. out-projection: fp16 concat only (bwd rows reversed back)  (BM=128)
    {
        TArgs ga = {};
        for (int b = 0; b < 2; b++) {
            ga.Ah[b] = yzh + (size_t)b * SL * DI;
            ga.Bh[b] = outWh + (size_t)b * DM * DI; ga.Bl[b] = outWl + (size_t)b * DM * DI;
            ga.bias[b] = outb[b];
            ga.Dh[b] = cth + b * DM;
            ga.rev[b] = (b == 1);
        }
        ga.M = SL; ga.N = DM; ga.K = DI; ga.ldd = 2 * DM;
        k_mma_gemm<0,2,128><<<dim3(DM / 128, SL / 128, 2), 256, SMEM128>>>(ga);
    }

    // 8. fusion: [2048 x 512], K=1024  (BM=128)
    {
        TArgs ga = {};
        ga.Ah[0] = ga.Ah[1] = cth;
        ga.Bh[0] = ga.Bh[1] = fuWh; ga.Bl[0] = ga.Bl[1] = fuWl;
        ga.bias[0] = ga.bias[1] = fub;
        ga.C[0] = ga.C[1] = out;
        ga.rev[0] = ga.rev[1] = 0;
        ga.M = SL; ga.N = DM; ga.K = 2 * DM; ga.ldc = DM;
        k_mma_gemm<0,0,128><<<dim3(DM / 128, SL / 128, 1), 256, SMEM128>>>(ga);
    }
}

// round 11
// speedup vs baseline: 1.7906x; 1.2397x over previous
#include <cuda_runtime.h>
#include <cuda_fp16.h>
#include <math.h>
#include <stdint.h>

#define SL   2048
#define DM   512
#define DI   1024
#define DS   16
#define DXZ  2048   // 2*DI
#define NSP  1056   // DI + 2*DS
#define NSP_PAD 1152
#define NCH  16
#define CL   128    // SL / NCH

// ---------------- fp32 scratch ----------------
__device__ float g_xz[2 * SL * DXZ];      // in-proj output: x_ssm | z
__device__ float g_xconv[2 * SL * DI];    // post depthwise conv (pre-silu)
__device__ float g_sp[2 * SL * NSP];      // xp-proj output: delta | B | C
__device__ float g_dt[2 * SL * DI];       // softplus(delta @ dtW + dtb)
// scan chunk scratch
__device__ float g_dtsum[2 * DI * NCH];
__device__ float g_hpart[2 * DI * NCH * DS];
__device__ float g_hinit[2 * DI * NCH * DS];

// ---------------- fp16 activations (A operands) ----------------
__device__ __align__(16) __half g_X2h[2 * SL * DM];
__device__ __align__(16) __half g_sxh[2 * SL * DI];
__device__ __align__(16) __half g_dh [2 * SL * DI];
__device__ __align__(16) __half g_yzh[2 * SL * DI];
__device__ __align__(16) __half g_cth[SL * 2 * DM];
// ---------------- fp16 transposed weights [Npad][K] ----------------
__device__ __align__(16) __half g_inW [2 * DXZ * DM];
__device__ __align__(16) __half g_xpW [2 * NSP_PAD * DI];
__device__ __align__(16) __half g_dtW [2 * DI * DI];
__device__ __align__(16) __half g_outW[2 * DM * DI];
__device__ __align__(16) __half g_fuW [DM * 2 * DM];

// ---------------- helpers ----------------
__device__ __forceinline__ float siluf(float v) { return v / (1.0f + __expf(-v)); }

__device__ __forceinline__ uint32_t smem_u32(const void* p) {
    uint32_t a;
    asm("{ .reg .u64 t; cvta.to.shared.u64 t, %1; cvt.u32.u64 %0, t; }" : "=r"(a) : "l"(p));
    return a;
}
__device__ __forceinline__ void cp16(uint32_t dst, const void* src) {
    asm volatile("cp.async.cg.shared.global [%0], [%1], 16;" :: "r"(dst), "l"(src));
}
__device__ __forceinline__ void cp_commit() {
    asm volatile("cp.async.commit_group;" ::: "memory");
}
__device__ __forceinline__ void cp_wait1() {
    asm volatile("cp.async.wait_group 1;" ::: "memory");
}

#define LDSM_X4(r0, r1, r2, r3, addr) \
    asm volatile("ldmatrix.sync.aligned.m8n8.x4.shared.b16 {%0,%1,%2,%3}, [%4];" \
                 : "=r"(r0), "=r"(r1), "=r"(r2), "=r"(r3) : "r"(addr))

#define MMA16816(d, a, b) \
    asm volatile("mma.sync.aligned.m16n8k16.row.col.f32.f16.f16.f32 " \
                 "{%0,%1,%2,%3}, {%4,%5,%6,%7}, {%8,%9}, {%0,%1,%2,%3};" \
                 : "+f"((d)[0]), "+f"((d)[1]), "+f"((d)[2]), "+f"((d)[3]) \
                 : "r"((a)[0]), "r"((a)[1]), "r"((a)[2]), "r"((a)[3]), \
                   "r"((b)[0]), "r"((b)[1]))

#define SWZ(o) ((o) ^ (((o) >> 3) & 0x70))

// ---------------- prepare: x -> fwd + reversed bwd fp16 ----------------
__global__ void k_prepare(const float* __restrict__ x) {
    int idx = blockIdx.x * blockDim.x + threadIdx.x;
    if (idx < SL * DM) {
        int l = idx / DM, d = idx % DM;
        __half h = __float2half(x[idx]);
        g_X2h[idx] = h;
        g_X2h[(size_t)SL * DM + (size_t)(SL - 1 - l) * DM + d] = h;
    }
}

// ---------------- causal depthwise conv (K=4); fp32 xconv + fp16 silu ----------------
__global__ void k_conv(const float* __restrict__ fcw, const float* __restrict__ fcb,
                       const float* __restrict__ bcw, const float* __restrict__ bcb) {
    int idx = blockIdx.x * blockDim.x + threadIdx.x;
    if (idx >= 2 * SL * DI) return;
    int b = idx / (SL * DI);
    int r = idx - b * SL * DI;
    int l = r / DI, d = r % DI;
    const float* cw = b ? bcw : fcw;
    const float* cb = b ? bcb : fcb;
    const float* xs = g_xz + (size_t)b * SL * DXZ;
    float acc = cb[d];
#pragma unroll
    for (int k = 0; k < 4; k++) {
        int ls = l + k - 3;
        if (ls >= 0) acc += cw[d * 4 + k] * xs[(size_t)ls * DXZ + d];
    }
    g_xconv[idx] = acc;
    g_sxh[idx] = __float2half(siluf(acc));
}

// ---------------- fused weight transpose to fp16 (all 9 weights, 1 launch) ----------------
struct WtJobs {
    const float* W[9];
    __half* Bt[9];
    int K[9], N[9], bx[9];
    int ofs[10];
};

__global__ void k_wt_all(WtJobs jw) {
    __shared__ float s[32][33];
    int bxg = blockIdx.x;
    int j = 0;
#pragma unroll
    for (int q = 0; q < 9; q++) if (bxg >= jw.ofs[q + 1]) j = q + 1;
    int local = bxg - jw.ofs[j];
    int K = jw.K[j], N = jw.N[j], bxn = jw.bx[j];
    int nb = (local % bxn) * 32, kb = (local / bxn) * 32;
    const float* __restrict__ W = jw.W[j];
    __half* __restrict__ Bt = jw.Bt[j];
    int tx = threadIdx.x, ty = threadIdx.y;
#pragma unroll
    for (int q = 0; q < 32; q += 8) {
        int k = kb + ty + q, n = nb + tx;
        s[ty + q][tx] = (n < N) ? W[(size_t)k * N + n] : 0.0f;
    }
    __syncthreads();
#pragma unroll
    for (int q = 0; q < 32; q += 8) {
        int n = nb + ty + q, k = kb + tx;
        Bt[(size_t)n * K + k] = __float2half(s[tx][ty + q]);
    }
}

// ---------------- fp16 1-term GEMM: C = A @ W^T + bias ----------------
// Template BM: CTA tile BM x 128, K-slab 64, 8 warps, 2-stage cp.async pipeline.
struct TArgs {
    const __half *Ah[2], *Bh[2];
    const float* bias[2];
    float* C[2];
    __half* Dh[2];
    int M, N, K, ldc, ldd, dlim;
    int rev[2];
};

#define BTILE_B 16384      // 128 x 64 fp16

// EPI: 0 none, 1 softplus.  MODE: 0 fp32 C, 1 fp32 C + fp16 D (cols<dlim), 2 fp16 D only.
template <int EPI, int MODE, int BM>
__global__ void __launch_bounds__(256, 1) k_mma_gemm(TArgs ga) {
    constexpr int MI = BM / 64;              // m microtiles per warp
    constexpr int TILE_A = BM * 128;
    constexpr int STG = TILE_A + BTILE_B;
    extern __shared__ __align__(1024) char smem[];
    const int bz = blockIdx.z;
    const __half* __restrict__ Ah = ga.Ah[bz];
    const __half* __restrict__ Bh = ga.Bh[bz];
    const float* __restrict__ bias = ga.bias[bz];
    float* __restrict__ C = ga.C[bz];
    __half* __restrict__ D = ga.Dh[bz];
    const int K = ga.K, N = ga.N, ldc = ga.ldc, ldd = ga.ldd, rev = ga.rev[bz];
    const int m0 = blockIdx.y * BM, n0 = blockIdx.x * 128;

    const int tid = threadIdx.x, wid = tid >> 5, lane = tid & 31;
    const int wm = (wid & 3) * (16 * MI);
    const int wn = (wid >> 2) * 64;
    const uint32_t sb = smem_u32(smem);

    float acc[MI][8][4];
#pragma unroll
    for (int i = 0; i < MI; i++)
#pragma unroll
        for (int j = 0; j < 8; j++)
#pragma unroll
            for (int q = 0; q < 4; q++) acc[i][j][q] = 0.0f;

    const int nslab = K / 64;
    const __half* Abase = Ah + (size_t)m0 * K;
    const __half* Bbase = Bh + (size_t)n0 * K;

    auto load_slab = [&](uint32_t sdst, int kslab) {
        const int kof = kslab * 64;
#pragma unroll
        for (int i = 0; i < BM / 32; i++) {
            int idx = tid + i * 256;
            int r = idx >> 3, c = idx & 7;
            cp16(sdst + SWZ(r * 128 + c * 16), Abase + (size_t)r * K + kof + c * 8);
        }
#pragma unroll
        for (int i = 0; i < 4; i++) {
            int idx = tid + i * 256;
            int r = idx >> 3, c = idx & 7;
            cp16(sdst + TILE_A + SWZ(r * 128 + c * 16), Bbase + (size_t)r * K + kof + c * 8);
        }
    };

    load_slab(sb, 0);
    cp_commit();
    if (nslab > 1) load_slab(sb + STG, 1);
    cp_commit();

    const int a_row = (lane & 15);
    const int a_kc  = (lane >> 4) * 16;
    const int b_row = (lane & 7) + ((lane >> 4) << 3);
    const int b_kc  = ((lane >> 3) & 1) * 16;

    for (int sl = 0; sl < nslab; sl++) {
        cp_wait1();
        __syncthreads();
        const uint32_t st = sb + (sl & 1) * STG;
        const uint32_t stA = st, stB = st + TILE_A;

#pragma unroll
        for (int ks = 0; ks < 4; ks++) {
            uint32_t ah[MI][4];
#pragma unroll
            for (int mi = 0; mi < MI; mi++) {
                uint32_t off = SWZ((wm + mi * 16 + a_row) * 128 + ks * 32 + a_kc);
                LDSM_X4(ah[mi][0], ah[mi][1], ah[mi][2], ah[mi][3], stA + off);
            }
            uint32_t bh[8][2];
#pragma unroll
            for (int jj = 0; jj < 4; jj++) {
                uint32_t off = SWZ((wn + jj * 16 + b_row) * 128 + ks * 32 + b_kc);
                uint32_t r0, r1, r2, r3;
                LDSM_X4(r0, r1, r2, r3, stB + off);
                bh[jj * 2][0] = r0; bh[jj * 2][1] = r1;
                bh[jj * 2 + 1][0] = r2; bh[jj * 2 + 1][1] = r3;
            }
#pragma unroll
            for (int mi = 0; mi < MI; mi++)
#pragma unroll
                for (int nj = 0; nj < 8; nj++)
                    MMA16816(acc[mi][nj], ah[mi], bh[nj]);
        }
        __syncthreads();
        if (sl + 2 < nslab) load_slab(sb + (sl & 1) * STG, sl + 2);
        cp_commit();
    }

    // epilogue
    const int gid = lane >> 2, tig = lane & 3;
#pragma unroll
    for (int mi = 0; mi < MI; mi++) {
        int mb = m0 + wm + mi * 16 + gid;
        int r1 = rev ? (ga.M - 1 - mb) : mb;
        int r2 = rev ? (ga.M - 1 - (mb + 8)) : (mb + 8);
#pragma unroll
        for (int nj = 0; nj < 8; nj++) {
            int nc = n0 + wn + nj * 8 + tig * 2;
            if (nc < N) {
                float b0 = bias[nc], b1 = bias[nc + 1];
                float v0 = acc[mi][nj][0] + b0;
                float v1 = acc[mi][nj][1] + b1;
                float v2 = acc[mi][nj][2] + b0;
                float v3 = acc[mi][nj][3] + b1;
                if (EPI == 1) {
                    v0 = (v0 > 20.0f) ? v0 : log1pf(__expf(v0));
                    v1 = (v1 > 20.0f) ? v1 : log1pf(__expf(v1));
                    v2 = (v2 > 20.0f) ? v2 : log1pf(__expf(v2));
                    v3 = (v3 > 20.0f) ? v3 : log1pf(__expf(v3));
                }
                if (MODE == 0 || MODE == 1) {
                    *(float2*)&C[(size_t)r1 * ldc + nc] = make_float2(v0, v1);
                    *(float2*)&C[(size_t)r2 * ldc + nc] = make_float2(v2, v3);
                }
                if ((MODE == 1 && nc < ga.dlim) || MODE == 2) {
                    *(__half2*)&D[(size_t)r1 * ldd + nc] = __floats2half2_rn(v0, v1);
                    *(__half2*)&D[(size_t)r2 * ldd + nc] = __floats2half2_rn(v2, v3);
                }
            }
        }
    }
}

#define SMEM128 (2 * (128 * 128 + BTILE_B))   // 65536
#define SMEM256 (2 * (256 * 128 + BTILE_B))   // 98304

// ---------------- chunked selective scan ----------------
__global__ void k_scanA(const float* __restrict__ A_log) {
    __shared__ float sB[CL][DS];
    const int b = blockIdx.z, ch = blockIdx.y;
    const int d = blockIdx.x * 128 + threadIdx.x;
    const float* __restrict__ spp = g_sp + (size_t)b * SL * NSP;
    for (int i = threadIdx.x; i < CL * DS; i += 128) {
        int l = i >> 4, s = i & 15;
        sB[l][s] = spp[(size_t)(ch * CL + l) * NSP + DI + s];
    }
    __syncthreads();
    float Ac[DS];
#pragma unroll
    for (int s = 0; s < DS; s++) Ac[s] = -__expf(A_log[d * DS + s]);
    float h[DS];
#pragma unroll
    for (int s = 0; s < DS; s++) h[s] = 0.0f;
    float dts = 0.0f;
    const float* __restrict__ dtp = g_dt + (size_t)b * SL * DI;
    const float* __restrict__ xcp = g_xconv + (size_t)b * SL * DI;
    for (int l = 0; l < CL; l++) {
        int gl = ch * CL + l;
        float dt = dtp[(size_t)gl * DI + d];
        float xv = xcp[(size_t)gl * DI + d];
        dts += dt;
        float du = dt * xv;
#pragma unroll
        for (int s = 0; s < DS; s++) h[s] = __expf(dt * Ac[s]) * h[s] + du * sB[l][s];
    }
    size_t base = ((size_t)(b * DI + d) * NCH + ch) * DS;
#pragma unroll
    for (int s = 0; s < DS; s++) g_hpart[base + s] = h[s];
    g_dtsum[(size_t)(b * DI + d) * NCH + ch] = dts;
}

__global__ void k_scanB(const float* __restrict__ A_log) {
    int idx = blockIdx.x * 256 + threadIdx.x;
    if (idx >= 2 * DI * DS) return;
    int s = idx & 15;
    int d = (idx >> 4) & (DI - 1);
    int b = idx >> 14;
    float Ac = -__expf(A_log[d * DS + s]);
    float h = 0.0f;
    size_t bd = (size_t)(b * DI + d) * NCH;
    for (int ch = 0; ch < NCH; ch++) {
        g_hinit[(bd + ch) * DS + s] = h;
        h = __expf(g_dtsum[bd + ch] * Ac) * h + g_hpart[(bd + ch) * DS + s];
    }
}

__global__ void k_scanC(const float* __restrict__ A_log, const float* __restrict__ Dp) {
    __shared__ float sB[CL][DS];
    __shared__ float sC[CL][DS];
    const int b = blockIdx.z, ch = blockIdx.y;
    const int d = blockIdx.x * 128 + threadIdx.x;
    const float* __restrict__ spp = g_sp + (size_t)b * SL * NSP;
    for (int i = threadIdx.x; i < CL * DS; i += 128) {
        int l = i >> 4, s = i & 15;
        sB[l][s] = spp[(size_t)(ch * CL + l) * NSP + DI + s];
        sC[l][s] = spp[(size_t)(ch * CL + l) * NSP + DI + DS + s];
    }
    __syncthreads();
    float Ac[DS];
#pragma unroll
    for (int s = 0; s < DS; s++) Ac[s] = -__expf(A_log[d * DS + s]);
    float h[DS];
    size_t hbase = ((size_t)(b * DI + d) * NCH + ch) * DS;
#pragma unroll
    for (int s = 0; s < DS; s++) h[s] = g_hinit[hbase + s];
    const float Dv = Dp[d];
    const float* __restrict__ dtp = g_dt + (size_t)b * SL * DI;
    const float* __restrict__ xcp = g_xconv + (size_t)b * SL * DI;
    const float* __restrict__ zp  = g_xz + (size_t)b * SL * DXZ + DI;
    __half* __restrict__ yh = g_yzh + (size_t)b * SL * DI;
    for (int l = 0; l < CL; l++) {
        int gl = ch * CL + l;
        float dt = dtp[(size_t)gl * DI + d];
        float xv = xcp[(size_t)gl * DI + d];
        float du = dt * xv;
        float y = Dv * xv;
#pragma unroll
        for (int s = 0; s < DS; s++) {
            h[s] = __expf(dt * Ac[s]) * h[s] + du * sB[l][s];
            y += h[s] * sC[l][s];
        }
        float zv = zp[(size_t)gl * DXZ + d];
        yh[(size_t)gl * DI + d] = __float2half(y * siluf(zv));
    }
}

// ---------------- host orchestration ----------------
extern "C" void kernel_launch(void* const* d_in, const int* in_sizes, int n_in,
                              void* d_out, int out_size) {
    const float* x = (const float*)d_in[0];
    const float* inW[2]  = {(const float*)d_in[1],  (const float*)d_in[11]};
    const float* inb[2]  = {(const float*)d_in[2],  (const float*)d_in[12]};
    const float* cw[2]   = {(const float*)d_in[3],  (const float*)d_in[13]};
    const float* cb[2]   = {(const float*)d_in[4],  (const float*)d_in[14]};
    const float* xpW[2]  = {(const float*)d_in[5],  (const float*)d_in[15]};
    const float* xpb[2]  = {(const float*)d_in[6],  (const float*)d_in[16]};
    const float* dtW[2]  = {(const float*)d_in[7],  (const float*)d_in[17]};
    const float* dtb[2]  = {(const float*)d_in[8],  (const float*)d_in[18]};
    const float* outW[2] = {(const float*)d_in[9],  (const float*)d_in[19]};
    const float* outb[2] = {(const float*)d_in[10], (const float*)d_in[20]};
    const float* A_log   = (const float*)d_in[21];
    const float* Dp      = (const float*)d_in[22];
    const float* fuW     = (const float*)d_in[23];
    const float* fub     = (const float*)d_in[24];
    float* out = (float*)d_out;

    cudaFuncSetAttribute(k_mma_gemm<0,0,256>, cudaFuncAttributeMaxDynamicSharedMemorySize, SMEM256);
    cudaFuncSetAttribute(k_mma_gemm<0,1,256>, cudaFuncAttributeMaxDynamicSharedMemorySize, SMEM256);
    cudaFuncSetAttribute(k_mma_gemm<1,0,256>, cudaFuncAttributeMaxDynamicSharedMemorySize, SMEM256);
    cudaFuncSetAttribute(k_mma_gemm<0,2,128>, cudaFuncAttributeMaxDynamicSharedMemorySize, SMEM128);
    cudaFuncSetAttribute(k_mma_gemm<0,0,128>, cudaFuncAttributeMaxDynamicSharedMemorySize, SMEM128);

    float *xz, *sp, *dtbuf;
    __half *X2h, *sxh, *dh, *yzh, *cth;
    __half *inWt, *xpWt, *dtWt, *outWt, *fuWt;
    cudaGetSymbolAddress((void**)&xz, g_xz);
    cudaGetSymbolAddress((void**)&sp, g_sp);
    cudaGetSymbolAddress((void**)&dtbuf, g_dt);
    cudaGetSymbolAddress((void**)&X2h, g_X2h);
    cudaGetSymbolAddress((void**)&sxh, g_sxh);
    cudaGetSymbolAddress((void**)&dh, g_dh);
    cudaGetSymbolAddress((void**)&yzh, g_yzh);
    cudaGetSymbolAddress((void**)&cth, g_cth);
    cudaGetSymbolAddress((void**)&inWt, g_inW);
    cudaGetSymbolAddress((void**)&xpWt, g_xpW);
    cudaGetSymbolAddress((void**)&dtWt, g_dtW);
    cudaGetSymbolAddress((void**)&outWt, g_outW);
    cudaGetSymbolAddress((void**)&fuWt, g_fuW);

    // 0. fused weight transpose (9 jobs, 1 launch)
    {
        WtJobs jw;
        const float* Ws[9] = {inW[0], inW[1], xpW[0], xpW[1], dtW[0], dtW[1], outW[0], outW[1], fuW};
        __half* Ts[9] = {inWt, inWt + (size_t)DXZ * DM, xpWt, xpWt + (size_t)NSP_PAD * DI,
                         dtWt, dtWt + (size_t)DI * DI, outWt, outWt + (size_t)DM * DI, fuWt};
        int Ks[9]  = {DM, DM, DI, DI, DI, DI, DI, DI, 2 * DM};
        int Ns[9]  = {DXZ, DXZ, NSP, NSP, DI, DI, DM, DM, DM};
        int Nps[9] = {DXZ, DXZ, NSP_PAD, NSP_PAD, DI, DI, DM, DM, DM};
        int ofs = 0;
        jw.ofs[0] = 0;
        for (int j = 0; j < 9; j++) {
            jw.W[j] = Ws[j]; jw.Bt[j] = Ts[j];
            jw.K[j] = Ks[j]; jw.N[j] = Ns[j]; jw.bx[j] = Nps[j] / 32;
            ofs += (Nps[j] / 32) * (Ks[j] / 32);
            jw.ofs[j + 1] = ofs;
        }
        k_wt_all<<<ofs, dim3(32, 8)>>>(jw);
    }

    // 1. prepare inputs
    k_prepare<<<(SL * DM + 255) / 256, 256>>>(x);

    // 2. in-projection: [2048 x 2048], K=512  (BM=256)
    {
        TArgs ga = {};
        for (int b = 0; b < 2; b++) {
            ga.Ah[b] = X2h + (size_t)b * SL * DM;
            ga.Bh[b] = inWt + (size_t)b * DXZ * DM;
            ga.bias[b] = inb[b];
            ga.C[b] = xz + (size_t)b * SL * DXZ;
            ga.rev[b] = 0;
        }
        ga.M = SL; ga.N = DXZ; ga.K = DM; ga.ldc = DXZ;
        k_mma_gemm<0,0,256><<<dim3(DXZ / 128, SL / 256, 2), 256, SMEM256>>>(ga);
    }

    // 3. depthwise conv + silu (fp16 out)
    k_conv<<<(2 * SL * DI + 255) / 256, 256>>>(cw[0], cb[0], cw[1], cb[1]);

    // 4. xp-projection: fp32 sp + fused fp16 delta split  (BM=256)
    {
        TArgs ga = {};
        for (int b = 0; b < 2; b++) {
            ga.Ah[b] = sxh + (size_t)b * SL * DI;
            ga.Bh[b] = xpWt + (size_t)b * NSP_PAD * DI;
            ga.bias[b] = xpb[b];
            ga.C[b] = sp + (size_t)b * SL * NSP;
            ga.Dh[b] = dh + (size_t)b * SL * DI;
            ga.rev[b] = 0;
        }
        ga.M = SL; ga.N = NSP; ga.K = DI; ga.ldc = NSP; ga.ldd = DI; ga.dlim = DI;
        k_mma_gemm<0,1,256><<<dim3(NSP_PAD / 128, SL / 256, 2), 256, SMEM256>>>(ga);
    }

    // 5. dt-projection + softplus: [2048 x 1024], K=1024  (BM=256)
    {
        TArgs ga = {};
        for (int b = 0; b < 2; b++) {
            ga.Ah[b] = dh + (size_t)b * SL * DI;
            ga.Bh[b] = dtWt + (size_t)b * DI * DI;
            ga.bias[b] = dtb[b];
            ga.C[b] = dtbuf + (size_t)b * SL * DI;
            ga.rev[b] = 0;
        }
        ga.M = SL; ga.N = DI; ga.K = DI; ga.ldc = DI;
        k_mma_gemm<1,0,256><<<dim3(DI / 128, SL / 256, 2), 256, SMEM256>>>(ga);
    }

    // 6. chunked selective scan
    k_scanA<<<dim3(DI / 128, NCH, 2), 128>>>(A_log);
    k_scanB<<<(2 * DI * DS + 255) / 256, 256>>>(A_log);
    k_scanC<<<dim3(DI / 128, NCH, 2), 128>>>(A_log, Dp);

    // 7. out-projection: fp16 concat only (bwd rows reversed back)  (BM=128)
    {
        TArgs ga = {};
        for (int b = 0; b < 2; b++) {
            ga.Ah[b] = yzh + (size_t)b * SL * DI;
            ga.Bh[b] = outWt + (size_t)b * DM * DI;
            ga.bias[b] = outb[b];
            ga.Dh[b] = cth + b * DM;
            ga.rev[b] = (b == 1);
        }
        ga.M = SL; ga.N = DM; ga.K = DI; ga.ldd = 2 * DM;
        k_mma_gemm<0,2,128><<<dim3(DM / 128, SL / 128, 2), 256, SMEM128>>>(ga);
    }

    // 8. fusion: [2048 x 512], K=1024  (BM=128)
    {
        TArgs ga = {};
        ga.Ah[0] = ga.Ah[1] = cth;
        ga.Bh[0] = ga.Bh[1] = fuWt;
        ga.bias[0] = ga.bias[1] = fub;
        ga.C[0] = ga.C[1] = out;
        ga.rev[0] = ga.rev[1] = 0;
        ga.M = SL; ga.N = DM; ga.K = 2 * DM; ga.ldc = DM;
        k_mma_gemm<0,0,128><<<dim3(DM / 128, SL / 128, 1), 256, SMEM128>>>(ga);
    }
}